// round 15
// baseline (speedup 1.0000x reference)
#include <cuda_runtime.h>
#include <cuda_bf16.h>
#include <math.h>
#include <stdint.h>

// ---------------------------------------------------------------------------
// Problem dimensions (compile-time)
// ---------------------------------------------------------------------------
#define D_MODEL   768
#define D_STATE   64
#define D_CONV    4
#define D_SSM     1536
#define HEADDIM   64
#define NHEADS    24
#define CONV_DIM  1664
#define D_IN_PROJ 3224
#define BB        2
#define LL        512
#define BL        (BB*LL)
#define QC        64
#define NCHUNK    (LL/QC)
#define NBHC      (BB*NHEADS*NCHUNK)

#define DT_OFF    (D_SSM + CONV_DIM)
#define LOG1EM6   (-13.815510558f)

#define UN_F      (BL * D_MODEL)        // 786432
#define WIN_F     (D_IN_PROJ * D_MODEL) // 2476032
#define WOUT_F    (D_MODEL * D_SSM)     // 1179648

// ---------------------------------------------------------------------------
// Scratch (static device globals)
// ---------------------------------------------------------------------------
__device__ float g_zxbcdt[BL * D_IN_PROJ];
__device__ float g_xbc[BL * CONV_DIM];      // tf32-rounded conv output
__device__ float g_dt[BL * NHEADS];
__device__ float g_ldA[BL * NHEADS];
__device__ float g_y[BL * D_SSM];           // tf32-rounded gated output
__device__ float g_T[NBHC * HEADDIM * D_STATE];
__device__ float g_S[NBHC * HEADDIM * D_STATE]; // tf32-rounded chunk states
__device__ float g_ai[NBHC * QC];
__device__ float g_laend[NBHC];
__device__ float g_uc[UN_F];                // tf32-rounded u
__device__ float g_Wic[WIN_F];              // tf32-rounded W_in
__device__ float g_Woc[WOUT_F];             // tf32-rounded W_out

// ---------------------------------------------------------------------------
// TF32 helpers
// ---------------------------------------------------------------------------
__device__ __forceinline__ uint32_t f2tf(float x) {
    uint32_t r;
    asm("cvt.rna.tf32.f32 %0, %1;" : "=r"(r) : "f"(x));
    return r;
}
__device__ __forceinline__ float tfr(float x) {
    return __uint_as_float(f2tf(x));
}

__device__ __forceinline__ void mma8(float* d, const uint32_t* a, const uint32_t* b) {
    asm volatile(
        "mma.sync.aligned.m16n8k8.row.col.f32.tf32.tf32.f32 "
        "{%0,%1,%2,%3},{%4,%5,%6,%7},{%8,%9},{%0,%1,%2,%3};"
        : "+f"(d[0]), "+f"(d[1]), "+f"(d[2]), "+f"(d[3])
        : "r"(a[0]), "r"(a[1]), "r"(a[2]), "r"(a[3]), "r"(b[0]), "r"(b[1]));
}

__device__ __forceinline__ void cp16(uint32_t dst, const void* src, bool pred) {
    int bytes = pred ? 16 : 0;
    asm volatile("cp.async.cg.shared.global [%0], [%1], 16, %2;\n"
                 :: "r"(dst), "l"(src), "r"(bytes));
}

// ---------------------------------------------------------------------------
// tf32 pre-round: u, W_in, W_out  ->  g_uc, g_Wic, g_Woc  (float4 stream)
// ---------------------------------------------------------------------------
__global__ void tf32_prep_kernel(const float4* __restrict__ u,
                                 const float4* __restrict__ Wi,
                                 const float4* __restrict__ Wo,
                                 float4* __restrict__ uc,
                                 float4* __restrict__ Wic,
                                 float4* __restrict__ Woc)
{
    int i = blockIdx.x * blockDim.x + threadIdx.x;
    const int n0 = UN_F / 4, n1 = WIN_F / 4, n2 = WOUT_F / 4;
    float4 v; float4* dst;
    if (i < n0)                { v = u[i];            dst = uc + i; }
    else if (i < n0 + n1)      { v = Wi[i - n0];      dst = Wic + (i - n0); }
    else if (i < n0 + n1 + n2) { v = Wo[i - n0 - n1]; dst = Woc + (i - n0 - n1); }
    else return;
    v.x = tfr(v.x); v.y = tfr(v.y); v.z = tfr(v.z); v.w = tfr(v.w);
    *dst = v;
}

// ---------------------------------------------------------------------------
// TF32 MMA GEMM:  C[m, n_base + n] = sum_k A[m,k] * W[n_base+n,k]
// 2-stage cp.async, 256 threads, warp grid 2(m) x 4(n).
// 1x block-cols: pre-rounded operands, scalar LDS fragments (no cvt);
// x3 block-cols (n0 in [x3col0,x3col1)): RAW staging + tf32x3 hi/lo.
// ---------------------------------------------------------------------------
template<int BM, int BN>
__global__ __launch_bounds__(256, 4) void mma_gemm(
    const float* __restrict__ Acv, const float* __restrict__ Araw,
    const float* __restrict__ Wcv, const float* __restrict__ Wraw,
    float* __restrict__ Cout, int Nw, int Nv, int Nstride, int K,
    int x3col0, int x3col1, int n_base)
{
    constexpr int MT = BM / 32;
    constexpr int NT = BN / 32;
    constexpr int SK = 36;

    extern __shared__ float sm_f[];
    float* smA = sm_f;                   // [2][BM][SK]
    float* smW = sm_f + 2 * BM * SK;     // [2][BN][SK]

    const int tid  = threadIdx.x;
    const int lane = tid & 31;
    const int warp = tid >> 5;
    const int wm0  = (warp & 1) * (BM / 2);
    const int wn0  = (warp >> 1) * (BN / 4);
    const int m0   = blockIdx.y * BM;
    const int n0   = n_base + blockIdx.x * BN;
    const bool x3  = (n0 >= x3col0) && (n0 < x3col1);
    const int gr   = lane >> 2;
    const int lk   = lane & 3;

    const float* Ap = x3 ? Araw : Acv;
    const float* Wp = x3 ? Wraw : Wcv;

    uint32_t smA_u = (uint32_t)__cvta_generic_to_shared(smA);
    uint32_t smW_u = (uint32_t)__cvta_generic_to_shared(smW);

    float acc[MT][NT][4];
#pragma unroll
    for (int mi = 0; mi < MT; mi++)
#pragma unroll
        for (int ni = 0; ni < NT; ni++)
#pragma unroll
            for (int r = 0; r < 4; r++) acc[mi][ni][r] = 0.f;

    auto load_stage = [&](int s, int kt) {
#pragma unroll
        for (int i = 0; i < BM * 8 / 256; i++) {
            int idx = tid + i * 256;
            int row = idx >> 3, c4 = idx & 7;
            cp16(smA_u + (uint32_t)(s * BM * SK + row * SK + c4 * 4) * 4,
                 Ap + (size_t)(m0 + row) * K + kt + c4 * 4, true);
        }
#pragma unroll
        for (int i = 0; i < BN * 8 / 256; i++) {
            int idx = tid + i * 256;
            int row = idx >> 3, c4 = idx & 7;
            cp16(smW_u + (uint32_t)(s * BN * SK + row * SK + c4 * 4) * 4,
                 Wp + (size_t)(n0 + row) * K + kt + c4 * 4, (n0 + row) < Nw);
        }
        asm volatile("cp.async.commit_group;");
    };

    const int nk = K / 32;
    load_stage(0, 0);

    for (int kt = 0; kt < nk; kt++) {
        if (kt + 1 < nk) {
            load_stage((kt + 1) & 1, (kt + 1) * 32);
            asm volatile("cp.async.wait_group 1;");
        } else {
            asm volatile("cp.async.wait_group 0;");
        }
        __syncthreads();

        const float* sA = smA + (kt & 1) * BM * SK;
        const float* sW = smW + (kt & 1) * BN * SK;

#pragma unroll
        for (int k8 = 0; k8 < 4; k8++) {
            const int kb = k8 * 8 + lk;

            if (!x3) {
                uint32_t ua[MT][4], ub[NT][2];
#pragma unroll
                for (int mi = 0; mi < MT; mi++) {
                    int r = wm0 + mi * 16 + gr;
                    ua[mi][0] = __float_as_uint(sA[r * SK + kb]);
                    ua[mi][1] = __float_as_uint(sA[(r + 8) * SK + kb]);
                    ua[mi][2] = __float_as_uint(sA[r * SK + kb + 4]);
                    ua[mi][3] = __float_as_uint(sA[(r + 8) * SK + kb + 4]);
                }
#pragma unroll
                for (int ni = 0; ni < NT; ni++) {
                    int n = wn0 + ni * 8 + gr;
                    ub[ni][0] = __float_as_uint(sW[n * SK + kb]);
                    ub[ni][1] = __float_as_uint(sW[n * SK + kb + 4]);
                }
#pragma unroll
                for (int mi = 0; mi < MT; mi++)
#pragma unroll
                    for (int ni = 0; ni < NT; ni++)
                        mma8(acc[mi][ni], ua[mi], ub[ni]);
            } else {
                float ar[MT][4];
#pragma unroll
                for (int mi = 0; mi < MT; mi++) {
                    int r = wm0 + mi * 16 + gr;
                    ar[mi][0] = sA[r * SK + kb];
                    ar[mi][1] = sA[(r + 8) * SK + kb];
                    ar[mi][2] = sA[r * SK + kb + 4];
                    ar[mi][3] = sA[(r + 8) * SK + kb + 4];
                }
                float brr[NT][2];
#pragma unroll
                for (int ni = 0; ni < NT; ni++) {
                    int n = wn0 + ni * 8 + gr;
                    brr[ni][0] = sW[n * SK + kb];
                    brr[ni][1] = sW[n * SK + kb + 4];
                }
                uint32_t ubh[NT][2], ubl[NT][2];
#pragma unroll
                for (int ni = 0; ni < NT; ni++) {
#pragma unroll
                    for (int j = 0; j < 2; j++) {
                        uint32_t hh = f2tf(brr[ni][j]);
                        ubh[ni][j] = hh;
                        ubl[ni][j] = f2tf(brr[ni][j] - __uint_as_float(hh));
                    }
                }
#pragma unroll
                for (int mi = 0; mi < MT; mi++) {
                    uint32_t uah[4], ual[4];
#pragma unroll
                    for (int r = 0; r < 4; r++) {
                        uint32_t hh = f2tf(ar[mi][r]);
                        uah[r] = hh;
                        ual[r] = f2tf(ar[mi][r] - __uint_as_float(hh));
                    }
#pragma unroll
                    for (int ni = 0; ni < NT; ni++) {
                        mma8(acc[mi][ni], ual, ubh[ni]);
                        mma8(acc[mi][ni], uah, ubl[ni]);
                        mma8(acc[mi][ni], uah, ubh[ni]);
                    }
                }
            }
        }
        __syncthreads();
    }

#pragma unroll
    for (int mi = 0; mi < MT; mi++) {
        int row = m0 + wm0 + mi * 16 + gr;
#pragma unroll
        for (int ni = 0; ni < NT; ni++) {
            int col = n0 + wn0 + ni * 8 + lk * 2;
            if (col < Nv) {
                *(float2*)(Cout + (size_t)row * Nstride + col) =
                    make_float2(acc[mi][ni][0], acc[mi][ni][1]);
                *(float2*)(Cout + (size_t)(row + 8) * Nstride + col) =
                    make_float2(acc[mi][ni][2], acc[mi][ni][3]);
            }
        }
    }
}

// ---------------------------------------------------------------------------
// Fused conv+SiLU (4 rows per thread) + dt/ldA prep.
// Output xbc is TF32-ROUNDED so downstream mma fragments need no cvt.
// ---------------------------------------------------------------------------
#define NCONV_T ((BL/4) * CONV_DIM)
__global__ void conv_dt_kernel(const float* __restrict__ zx,
                               const float* __restrict__ cw,
                               const float* __restrict__ cb,
                               const float* __restrict__ dt_bias,
                               const float* __restrict__ A_log,
                               float* __restrict__ out,
                               float* __restrict__ dt_out,
                               float* __restrict__ ldA_out)
{
    int idx = blockIdx.x * blockDim.x + threadIdx.x;
    if (idx < NCONV_T) {
        int c  = idx % CONV_DIM;
        int q  = idx / CONV_DIM;
        int b  = q / (LL / 4);
        int l0 = (q % (LL / 4)) * 4;

        float w0 = cw[c * 4 + 0], w1 = cw[c * 4 + 1];
        float w2 = cw[c * 4 + 2], w3 = cw[c * 4 + 3];
        float bias = cb[c];

        float v[7];
#pragma unroll
        for (int j = 0; j < 7; j++) {
            int t = l0 - 3 + j;
            v[j] = (t >= 0) ? zx[(size_t)(b * LL + t) * D_IN_PROJ + D_SSM + c] : 0.f;
        }
#pragma unroll
        for (int r = 0; r < 4; r++) {
            float sum = bias;
            sum = fmaf(v[r],     w0, sum);
            sum = fmaf(v[r + 1], w1, sum);
            sum = fmaf(v[r + 2], w2, sum);
            sum = fmaf(v[r + 3], w3, sum);
            float sig = 1.f / (1.f + expf(-sum));
            out[(size_t)(b * LL + l0 + r) * CONV_DIM + c] = tfr(sum * sig);
        }
    } else if (idx < NCONV_T + BL * NHEADS) {
        int i2 = idx - NCONV_T;
        int h  = i2 % NHEADS;
        int bl = i2 / NHEADS;
        float raw = zx[(size_t)bl * D_IN_PROJ + DT_OFF + h] + dt_bias[h];
        float sp = fmaxf(raw, 0.f) + log1pf(expf(-fabsf(raw)));
        float dt = fminf(fmaxf(sp, 1e-6f), 1000.f);
        float A  = -expf(A_log[h]);
        dt_out[i2]  = dt;
        ldA_out[i2] = fmaxf(dt * A, LOG1EM6);
    }
}

// ---------------------------------------------------------------------------
// Chunk kernel — tf32 tensor-core; inputs pre-rounded, no cvt in hot loops
// (except GEMM3's A-fragment which is an fp32 product).
// ---------------------------------------------------------------------------
__global__ __launch_bounds__(256) void chunk_kernel(
    const float* __restrict__ xbc, const float* __restrict__ dtb,
    const float* __restrict__ lda, float* __restrict__ yintra,
    float* __restrict__ Tg, float* __restrict__ aig,
    float* __restrict__ laendg)
{
    extern __shared__ float sm[];
    float* sX  = sm;             // [64][65]  tf32 values
    float* sB  = sm + 4160;      // tf32 values
    float* sC  = sm + 8320;      // C (tf32) then G (rounded at write)
    float* sdt = sm + 12480;
    float* sla = sdt + 64;
    float* sw  = sla + 64;

    const int bhc = blockIdx.x;
    const int c = bhc & (NCHUNK - 1);
    const int h = (bhc >> 3) % NHEADS;
    const int b = bhc / (NCHUNK * NHEADS);
    const int tid  = threadIdx.x;
    const int lane = tid & 31;
    const int warp = tid >> 5;
    const int gr   = lane >> 2;
    const int lk   = lane & 3;
    const int wm0  = (warp & 1) * 32;
    const int wn0  = (warp >> 1) * 16;
    const int row0 = b * LL + c * QC;

#pragma unroll
    for (int idx = tid; idx < 64 * 16; idx += 256) {
        int i = idx >> 4, f = idx & 15;
        const float* rp = xbc + (size_t)(row0 + i) * CONV_DIM;
        float4 xv = *(const float4*)(rp + h * HEADDIM + f * 4);
        float4 bv = *(const float4*)(rp + D_SSM + f * 4);
        float4 cv = *(const float4*)(rp + D_SSM + D_STATE + f * 4);
        float* xr = sX + i * 65 + f * 4;
        xr[0] = xv.x; xr[1] = xv.y; xr[2] = xv.z; xr[3] = xv.w;
        float* br = sB + i * 65 + f * 4;
        br[0] = bv.x; br[1] = bv.y; br[2] = bv.z; br[3] = bv.w;
        float* cr = sC + i * 65 + f * 4;
        cr[0] = cv.x; cr[1] = cv.y; cr[2] = cv.z; cr[3] = cv.w;
    }
    if (tid < 64) {
        sdt[tid] = dtb[(row0 + tid) * NHEADS + h];
        sla[tid] = lda[(row0 + tid) * NHEADS + h];
    }
    __syncthreads();
    if (tid < 32) {
        float a = sla[tid];
#pragma unroll
        for (int o = 1; o < 32; o <<= 1) {
            float n = __shfl_up_sync(0xffffffffu, a, o);
            if (lane >= o) a += n;
        }
        float tot = __shfl_sync(0xffffffffu, a, 31);
        float bb2 = sla[32 + tid];
#pragma unroll
        for (int o = 1; o < 32; o <<= 1) {
            float n = __shfl_up_sync(0xffffffffu, bb2, o);
            if (lane >= o) bb2 += n;
        }
        sla[tid] = a;
        sla[32 + tid] = bb2 + tot;
    }
    __syncthreads();
    if (tid < 64) {
        sw[tid] = expf(sla[63] - sla[tid]) * sdt[tid];
        aig[bhc * QC + tid] = expf(sla[tid]);
        if (tid == 0) laendg[bhc] = sla[63];
    }

    // --- GEMM1: CB[i][j] = sum_n C[i,n] * B[j,n]  (operands pre-rounded) ---
    float acc1[2][2][4];
#pragma unroll
    for (int mi = 0; mi < 2; mi++)
#pragma unroll
        for (int ni = 0; ni < 2; ni++)
#pragma unroll
            for (int e = 0; e < 4; e++) acc1[mi][ni][e] = 0.f;

#pragma unroll
    for (int k8 = 0; k8 < 8; k8++) {
        int kb = k8 * 8 + lk;
        uint32_t ua[2][4], ub[2][2];
#pragma unroll
        for (int mi = 0; mi < 2; mi++) {
            int r = wm0 + mi * 16 + gr;
            ua[mi][0] = __float_as_uint(sC[r * 65 + kb]);
            ua[mi][1] = __float_as_uint(sC[(r + 8) * 65 + kb]);
            ua[mi][2] = __float_as_uint(sC[r * 65 + kb + 4]);
            ua[mi][3] = __float_as_uint(sC[(r + 8) * 65 + kb + 4]);
        }
#pragma unroll
        for (int ni = 0; ni < 2; ni++) {
            int j = wn0 + ni * 8 + gr;
            ub[ni][0] = __float_as_uint(sB[j * 65 + kb]);
            ub[ni][1] = __float_as_uint(sB[j * 65 + kb + 4]);
        }
#pragma unroll
        for (int mi = 0; mi < 2; mi++)
#pragma unroll
            for (int ni = 0; ni < 2; ni++)
                mma8(acc1[mi][ni], ua[mi], ub[ni]);
    }
    __syncthreads();

    // mask + scale into G (tf32-rounded at write; overwrites sC)
#pragma unroll
    for (int mi = 0; mi < 2; mi++) {
        int ilo = wm0 + mi * 16 + gr;
        int ihi = ilo + 8;
#pragma unroll
        for (int ni = 0; ni < 2; ni++) {
            int j0c = wn0 + ni * 8 + 2 * lk;
            int j1c = j0c + 1;
            float g00 = (j0c <= ilo) ? acc1[mi][ni][0] * sdt[j0c] * expf(sla[ilo] - sla[j0c]) : 0.f;
            float g01 = (j1c <= ilo) ? acc1[mi][ni][1] * sdt[j1c] * expf(sla[ilo] - sla[j1c]) : 0.f;
            float g10 = (j0c <= ihi) ? acc1[mi][ni][2] * sdt[j0c] * expf(sla[ihi] - sla[j0c]) : 0.f;
            float g11 = (j1c <= ihi) ? acc1[mi][ni][3] * sdt[j1c] * expf(sla[ihi] - sla[j1c]) : 0.f;
            sC[ilo * 65 + j0c] = tfr(g00);
            sC[ilo * 65 + j1c] = tfr(g01);
            sC[ihi * 65 + j0c] = tfr(g10);
            sC[ihi * 65 + j1c] = tfr(g11);
        }
    }
    __syncthreads();

    // --- GEMM2: Y[i][p] = sum_j G[i,j] * X[j,p]  (both pre-rounded) ---
    {
        float acc2[2][2][4];
#pragma unroll
        for (int mi = 0; mi < 2; mi++)
#pragma unroll
            for (int ni = 0; ni < 2; ni++)
#pragma unroll
                for (int e = 0; e < 4; e++) acc2[mi][ni][e] = 0.f;

#pragma unroll
        for (int k8 = 0; k8 < 8; k8++) {
            int kb = k8 * 8 + lk;
            uint32_t ua[2][4], ub[2][2];
#pragma unroll
            for (int mi = 0; mi < 2; mi++) {
                int r = wm0 + mi * 16 + gr;
                ua[mi][0] = __float_as_uint(sC[r * 65 + kb]);
                ua[mi][1] = __float_as_uint(sC[(r + 8) * 65 + kb]);
                ua[mi][2] = __float_as_uint(sC[r * 65 + kb + 4]);
                ua[mi][3] = __float_as_uint(sC[(r + 8) * 65 + kb + 4]);
            }
#pragma unroll
            for (int ni = 0; ni < 2; ni++) {
                int p = wn0 + ni * 8 + gr;
                ub[ni][0] = __float_as_uint(sX[kb * 65 + p]);
                ub[ni][1] = __float_as_uint(sX[(kb + 4) * 65 + p]);
            }
#pragma unroll
            for (int mi = 0; mi < 2; mi++)
#pragma unroll
                for (int ni = 0; ni < 2; ni++)
                    mma8(acc2[mi][ni], ua[mi], ub[ni]);
        }
#pragma unroll
        for (int mi = 0; mi < 2; mi++) {
            int ilo = wm0 + mi * 16 + gr;
#pragma unroll
            for (int ni = 0; ni < 2; ni++) {
                int pc = wn0 + ni * 8 + 2 * lk;
                *(float2*)(yintra + (size_t)(row0 + ilo) * D_SSM + h * HEADDIM + pc) =
                    make_float2(acc2[mi][ni][0], acc2[mi][ni][1]);
                *(float2*)(yintra + (size_t)(row0 + ilo + 8) * D_SSM + h * HEADDIM + pc) =
                    make_float2(acc2[mi][ni][2], acc2[mi][ni][3]);
            }
        }
    }

    // --- GEMM3: T[p][n] = sum_j (w_j * X[j,p]) * B[j,n] ---
    {
        float acc3[2][2][4];
#pragma unroll
        for (int mi = 0; mi < 2; mi++)
#pragma unroll
            for (int ni = 0; ni < 2; ni++)
#pragma unroll
                for (int e = 0; e < 4; e++) acc3[mi][ni][e] = 0.f;

#pragma unroll
        for (int k8 = 0; k8 < 8; k8++) {
            int kb = k8 * 8 + lk;
            float w0 = sw[kb], w1 = sw[kb + 4];
            uint32_t ua[2][4], ub[2][2];
#pragma unroll
            for (int mi = 0; mi < 2; mi++) {
                int r = wm0 + mi * 16 + gr;   // p index
                ua[mi][0] = f2tf(sX[kb * 65 + r] * w0);
                ua[mi][1] = f2tf(sX[kb * 65 + r + 8] * w0);
                ua[mi][2] = f2tf(sX[(kb + 4) * 65 + r] * w1);
                ua[mi][3] = f2tf(sX[(kb + 4) * 65 + r + 8] * w1);
            }
#pragma unroll
            for (int ni = 0; ni < 2; ni++) {
                int n = wn0 + ni * 8 + gr;
                ub[ni][0] = __float_as_uint(sB[kb * 65 + n]);
                ub[ni][1] = __float_as_uint(sB[(kb + 4) * 65 + n]);
            }
#pragma unroll
            for (int mi = 0; mi < 2; mi++)
#pragma unroll
                for (int ni = 0; ni < 2; ni++)
                    mma8(acc3[mi][ni], ua[mi], ub[ni]);
        }
#pragma unroll
        for (int mi = 0; mi < 2; mi++) {
            int plo = wm0 + mi * 16 + gr;
#pragma unroll
            for (int ni = 0; ni < 2; ni++) {
                int nc = wn0 + ni * 8 + 2 * lk;
                *(float2*)(Tg + (size_t)bhc * 4096 + plo * 64 + nc) =
                    make_float2(acc3[mi][ni][0], acc3[mi][ni][1]);
                *(float2*)(Tg + (size_t)bhc * 4096 + (plo + 8) * 64 + nc) =
                    make_float2(acc3[mi][ni][2], acc3[mi][ni][3]);
            }
        }
    }
}

// ---------------------------------------------------------------------------
// Parallel chunk-state combine: 768 blocks; Sg written tf32-rounded.
// ---------------------------------------------------------------------------
__global__ __launch_bounds__(256) void combine_kernel(
    const float* __restrict__ Tg, const float* __restrict__ laendg,
    float* __restrict__ Sg)
{
    const int bh  = blockIdx.x >> 4;
    const int e   = (blockIdx.x & 15) * 256 + threadIdx.x;
    float s = 0.f;
#pragma unroll
    for (int c = 0; c < NCHUNK; c++) {
        int bhc = bh * NCHUNK + c;
        Sg[(size_t)bhc * 4096 + e] = tfr(s);
        float ae = expf(__ldg(laendg + bhc));
        s = fmaf(ae, s, Tg[(size_t)bhc * 4096 + e]);
    }
}

// ---------------------------------------------------------------------------
// Inter-chunk contribution + skip + gating — tf32 mma; operands pre-rounded;
// writes y rounded to tf32 for out_proj.
// ---------------------------------------------------------------------------
__global__ __launch_bounds__(256) void inter_kernel(
    const float* __restrict__ xbc, const float* __restrict__ Sg,
    const float* __restrict__ aig, const float* __restrict__ zx,
    const float* __restrict__ Dp, float* __restrict__ y)
{
    __shared__ float sC[64 * 65];
    __shared__ float sS[64 * 65];
    __shared__ float sai[64];

    const int bhc = blockIdx.x;
    const int c = bhc & (NCHUNK - 1);
    const int h = (bhc >> 3) % NHEADS;
    const int b = bhc / (NCHUNK * NHEADS);
    const int tid  = threadIdx.x;
    const int lane = tid & 31;
    const int warp = tid >> 5;
    const int gr   = lane >> 2;
    const int lk   = lane & 3;
    const int wm0  = (warp & 1) * 32;
    const int wn0  = (warp >> 1) * 16;
    const int row0 = b * LL + c * QC;

#pragma unroll
    for (int idx = tid; idx < 64 * 16; idx += 256) {
        int i = idx >> 4, f = idx & 15;
        const float* rp = xbc + (size_t)(row0 + i) * CONV_DIM;
        float4 cv = *(const float4*)(rp + D_SSM + D_STATE + f * 4);
        float* cr = sC + i * 65 + f * 4;
        cr[0] = cv.x; cr[1] = cv.y; cr[2] = cv.z; cr[3] = cv.w;
        float4 sv = *(const float4*)(Sg + (size_t)bhc * 4096 + i * 64 + f * 4);
        float* sr = sS + i * 65 + f * 4;
        sr[0] = sv.x; sr[1] = sv.y; sr[2] = sv.z; sr[3] = sv.w;
    }
    if (tid < 64) sai[tid] = aig[bhc * QC + tid];
    __syncthreads();

    float acc[2][2][4];
#pragma unroll
    for (int mi = 0; mi < 2; mi++)
#pragma unroll
        for (int ni = 0; ni < 2; ni++)
#pragma unroll
            for (int e = 0; e < 4; e++) acc[mi][ni][e] = 0.f;

#pragma unroll
    for (int k8 = 0; k8 < 8; k8++) {
        int kb = k8 * 8 + lk;
        uint32_t ua[2][4], ub[2][2];
#pragma unroll
        for (int mi = 0; mi < 2; mi++) {
            int r = wm0 + mi * 16 + gr;
            ua[mi][0] = __float_as_uint(sC[r * 65 + kb]);
            ua[mi][1] = __float_as_uint(sC[(r + 8) * 65 + kb]);
            ua[mi][2] = __float_as_uint(sC[r * 65 + kb + 4]);
            ua[mi][3] = __float_as_uint(sC[(r + 8) * 65 + kb + 4]);
        }
#pragma unroll
        for (int ni = 0; ni < 2; ni++) {
            int p = wn0 + ni * 8 + gr;
            ub[ni][0] = __float_as_uint(sS[p * 65 + kb]);
            ub[ni][1] = __float_as_uint(sS[p * 65 + kb + 4]);
        }
#pragma unroll
        for (int mi = 0; mi < 2; mi++)
#pragma unroll
            for (int ni = 0; ni < 2; ni++)
                mma8(acc[mi][ni], ua[mi], ub[ni]);
    }

    const float Dv = Dp[h];
#pragma unroll
    for (int mi = 0; mi < 2; mi++) {
        int rows[2] = { wm0 + mi * 16 + gr, wm0 + mi * 16 + gr + 8 };
#pragma unroll
        for (int rr = 0; rr < 2; rr++) {
            int i = rows[rr];
            size_t r = row0 + i;
            float aiv = sai[i];
#pragma unroll
            for (int ni = 0; ni < 2; ni++) {
                int pc = wn0 + ni * 8 + 2 * lk;
                float a0 = acc[mi][ni][rr * 2 + 0];
                float a1 = acc[mi][ni][rr * 2 + 1];
                float2 xv = *(const float2*)(xbc + r * CONV_DIM + h * HEADDIM + pc);
                float2 zv = *(const float2*)(zx + r * D_IN_PROJ + h * HEADDIM + pc);
                float2 yv = *(float2*)(y + r * D_SSM + h * HEADDIM + pc);
                float y0 = yv.x + aiv * a0 + Dv * xv.x;
                float y1 = yv.y + aiv * a1 + Dv * xv.y;
                y0 *= zv.x * (1.f / (1.f + expf(-zv.x)));
                y1 *= zv.y * (1.f / (1.f + expf(-zv.y)));
                *(float2*)(y + r * D_SSM + h * HEADDIM + pc) =
                    make_float2(tfr(y0), tfr(y1));
            }
        }
    }
}

// ---------------------------------------------------------------------------
// Launch: main stream handles xBC+dt columns then the scan path; a second
// stream computes the z columns of in_proj concurrently (joined before inter).
// ---------------------------------------------------------------------------
extern "C" void kernel_launch(void* const* d_in, const int* in_sizes, int n_in,
                              void* d_out, int out_size)
{
    const float* u       = (const float*)d_in[0];
    const float* W_in    = (const float*)d_in[1];
    const float* conv_w  = (const float*)d_in[2];
    const float* conv_b  = (const float*)d_in[3];
    const float* dt_bias = (const float*)d_in[4];
    const float* A_log   = (const float*)d_in[5];
    const float* D_param = (const float*)d_in[6];
    const float* W_out   = (const float*)d_in[7];
    float* out = (float*)d_out;

    float *zx, *xbc, *dt, *ldA, *y, *Tg, *Sg, *aig, *laendg, *uc, *Wic, *Woc;
    cudaGetSymbolAddress((void**)&zx,     g_zxbcdt);
    cudaGetSymbolAddress((void**)&xbc,    g_xbc);
    cudaGetSymbolAddress((void**)&dt,     g_dt);
    cudaGetSymbolAddress((void**)&ldA,    g_ldA);
    cudaGetSymbolAddress((void**)&y,      g_y);
    cudaGetSymbolAddress((void**)&Tg,     g_T);
    cudaGetSymbolAddress((void**)&Sg,     g_S);
    cudaGetSymbolAddress((void**)&aig,    g_ai);
    cudaGetSymbolAddress((void**)&laendg, g_laend);
    cudaGetSymbolAddress((void**)&uc,     g_uc);
    cudaGetSymbolAddress((void**)&Wic,    g_Wic);
    cudaGetSymbolAddress((void**)&Woc,    g_Woc);

    static cudaStream_t s1 = nullptr;
    static cudaEvent_t evP = nullptr, evB = nullptr;
    static bool attr_done = false;
    if (!attr_done) {
        cudaFuncSetAttribute(chunk_kernel,
                             cudaFuncAttributeMaxDynamicSharedMemorySize, 51200);
        cudaFuncSetAttribute(mma_gemm<64, 128>,
                             cudaFuncAttributeMaxDynamicSharedMemorySize, 55296);
        cudaFuncSetAttribute(mma_gemm<64, 64>,
                             cudaFuncAttributeMaxDynamicSharedMemorySize, 36864);
        cudaStreamCreateWithFlags(&s1, cudaStreamNonBlocking);
        cudaEventCreateWithFlags(&evP, cudaEventDisableTiming);
        cudaEventCreateWithFlags(&evB, cudaEventDisableTiming);
        attr_done = true;
    }

    // 0) tf32 pre-round of u, W_in, W_out (main stream)
    {
        int n4 = (UN_F + WIN_F + WOUT_F) / 4;
        tf32_prep_kernel<<<(n4 + 255) / 256, 256>>>(
            (const float4*)u, (const float4*)W_in, (const float4*)W_out,
            (float4*)uc, (float4*)Wic, (float4*)Woc);
    }
    cudaEventRecord(evP, 0);
    cudaStreamWaitEvent(s1, evP, 0);

    // 1a) in_proj xBC+dt columns [1536,3328): main stream; x3 on [3072,3200)
    {
        dim3 grid(14, BL / 64);
        mma_gemm<64, 128><<<grid, 256, 55296>>>(
            uc, u, Wic, W_in, zx, D_IN_PROJ, D_IN_PROJ, D_IN_PROJ, D_MODEL,
            3072, 3200, 1536);
    }
    // 1b) in_proj z columns [0,1536): side stream (overlaps conv/chunk/combine)
    {
        dim3 grid(12, BL / 64);
        mma_gemm<64, 128><<<grid, 256, 55296, s1>>>(
            uc, u, Wic, W_in, zx, D_IN_PROJ, D_IN_PROJ, D_IN_PROJ, D_MODEL,
            1 << 30, 1 << 30, 0);
    }
    cudaEventRecord(evB, s1);

    // 2) conv + silu + dt/ldA (main stream; depends only on 1a)
    {
        int cnt = NCONV_T + BL * NHEADS;
        conv_dt_kernel<<<(cnt + 255) / 256, 256>>>(
            zx, conv_w, conv_b, dt_bias, A_log, xbc, dt, ldA);
    }
    // 3) chunked scan (main stream)
    chunk_kernel<<<NBHC, 256, 51200>>>(xbc, dt, ldA, y, Tg, aig, laendg);
    combine_kernel<<<BB * NHEADS * 16, 256>>>(Tg, laendg, Sg);

    // join: z columns must be ready before inter reads zx[:, 0:1536)
    cudaStreamWaitEvent(0, evB, 0);
    inter_kernel<<<NBHC, 256>>>(xbc, Sg, aig, zx, D_param, y);

    // 4) out_proj: 64x64 tiles, 192 blocks (main stream)
    {
        dim3 grid(D_MODEL / 64, BL / 64);
        mma_gemm<64, 64><<<grid, 256, 36864>>>(
            y, y, Woc, W_out, out, D_MODEL, D_MODEL, D_MODEL, D_SSM,
            1 << 30, 1 << 30, 0);
    }
}

// round 16
// speedup vs baseline: 1.0851x; 1.0851x over previous
#include <cuda_runtime.h>
#include <cuda_bf16.h>
#include <math.h>
#include <stdint.h>

// ---------------------------------------------------------------------------
// Problem dimensions (compile-time)
// ---------------------------------------------------------------------------
#define D_MODEL   768
#define D_STATE   64
#define D_CONV    4
#define D_SSM     1536
#define HEADDIM   64
#define NHEADS    24
#define CONV_DIM  1664
#define D_IN_PROJ 3224
#define BB        2
#define LL        512
#define BL        (BB*LL)
#define QC        64
#define NCHUNK    (LL/QC)
#define NBHC      (BB*NHEADS*NCHUNK)

#define DT_OFF    (D_SSM + CONV_DIM)
#define LOG1EM6   (-13.815510558f)

#define UN_F      (BL * D_MODEL)        // 786432
#define WIN_F     (D_IN_PROJ * D_MODEL) // 2476032
#define WOUT_F    (D_MODEL * D_SSM)     // 1179648

// ---------------------------------------------------------------------------
// Scratch (static device globals)
// ---------------------------------------------------------------------------
__device__ float g_zxbcdt[BL * D_IN_PROJ];
__device__ float g_xbc[BL * CONV_DIM];      // tf32-rounded conv output
__device__ float g_dt[BL * NHEADS];
__device__ float g_ldA[BL * NHEADS];
__device__ float g_y[BL * D_SSM];           // tf32-rounded gated output
__device__ float g_T[NBHC * HEADDIM * D_STATE];
__device__ float g_S[NBHC * HEADDIM * D_STATE]; // tf32-rounded chunk states
__device__ float g_ai[NBHC * QC];
__device__ float g_laend[NBHC];
__device__ float g_uc[UN_F];                // tf32-rounded u
__device__ float g_Wic[WIN_F];              // tf32-rounded W_in
__device__ float g_Woc[WOUT_F];             // tf32-rounded W_out

// ---------------------------------------------------------------------------
// TF32 helpers
// ---------------------------------------------------------------------------
__device__ __forceinline__ uint32_t f2tf(float x) {
    uint32_t r;
    asm("cvt.rna.tf32.f32 %0, %1;" : "=r"(r) : "f"(x));
    return r;
}
__device__ __forceinline__ float tfr(float x) {
    return __uint_as_float(f2tf(x));
}

__device__ __forceinline__ void mma8(float* d, const uint32_t* a, const uint32_t* b) {
    asm volatile(
        "mma.sync.aligned.m16n8k8.row.col.f32.tf32.tf32.f32 "
        "{%0,%1,%2,%3},{%4,%5,%6,%7},{%8,%9},{%0,%1,%2,%3};"
        : "+f"(d[0]), "+f"(d[1]), "+f"(d[2]), "+f"(d[3])
        : "r"(a[0]), "r"(a[1]), "r"(a[2]), "r"(a[3]), "r"(b[0]), "r"(b[1]));
}

__device__ __forceinline__ void cp16(uint32_t dst, const void* src, bool pred) {
    int bytes = pred ? 16 : 0;
    asm volatile("cp.async.cg.shared.global [%0], [%1], 16, %2;\n"
                 :: "r"(dst), "l"(src), "r"(bytes));
}

// ---------------------------------------------------------------------------
// tf32 pre-round: u, W_in, W_out  ->  g_uc, g_Wic, g_Woc  (float4 stream)
// ---------------------------------------------------------------------------
__global__ void tf32_prep_kernel(const float4* __restrict__ u,
                                 const float4* __restrict__ Wi,
                                 const float4* __restrict__ Wo,
                                 float4* __restrict__ uc,
                                 float4* __restrict__ Wic,
                                 float4* __restrict__ Woc)
{
    int i = blockIdx.x * blockDim.x + threadIdx.x;
    const int n0 = UN_F / 4, n1 = WIN_F / 4, n2 = WOUT_F / 4;
    float4 v; float4* dst;
    if (i < n0)                { v = u[i];            dst = uc + i; }
    else if (i < n0 + n1)      { v = Wi[i - n0];      dst = Wic + (i - n0); }
    else if (i < n0 + n1 + n2) { v = Wo[i - n0 - n1]; dst = Woc + (i - n0 - n1); }
    else return;
    v.x = tfr(v.x); v.y = tfr(v.y); v.z = tfr(v.z); v.w = tfr(v.w);
    *dst = v;
}

// ---------------------------------------------------------------------------
// TF32 MMA GEMM:  C[m, n] = sum_k A[m,k] * W[n,k]
// 2-stage cp.async, 256 threads, warp grid 2(m) x 4(n).
// 1x block-cols: pre-rounded operands, scalar LDS fragments (no cvt);
// x3 block-cols (n0 in [x3col0,x3col1)): RAW staging + tf32x3 hi/lo.
// ---------------------------------------------------------------------------
template<int BM, int BN>
__global__ __launch_bounds__(256, 4) void mma_gemm(
    const float* __restrict__ Acv, const float* __restrict__ Araw,
    const float* __restrict__ Wcv, const float* __restrict__ Wraw,
    float* __restrict__ Cout, int Nw, int Nv, int Nstride, int K,
    int x3col0, int x3col1)
{
    constexpr int MT = BM / 32;
    constexpr int NT = BN / 32;
    constexpr int SK = 36;

    extern __shared__ float sm_f[];
    float* smA = sm_f;                   // [2][BM][SK]
    float* smW = sm_f + 2 * BM * SK;     // [2][BN][SK]

    const int tid  = threadIdx.x;
    const int lane = tid & 31;
    const int warp = tid >> 5;
    const int wm0  = (warp & 1) * (BM / 2);
    const int wn0  = (warp >> 1) * (BN / 4);
    const int m0   = blockIdx.y * BM;
    const int n0   = blockIdx.x * BN;
    const bool x3  = (n0 >= x3col0) && (n0 < x3col1);
    const int gr   = lane >> 2;
    const int lk   = lane & 3;

    const float* Ap = x3 ? Araw : Acv;
    const float* Wp = x3 ? Wraw : Wcv;

    uint32_t smA_u = (uint32_t)__cvta_generic_to_shared(smA);
    uint32_t smW_u = (uint32_t)__cvta_generic_to_shared(smW);

    float acc[MT][NT][4];
#pragma unroll
    for (int mi = 0; mi < MT; mi++)
#pragma unroll
        for (int ni = 0; ni < NT; ni++)
#pragma unroll
            for (int r = 0; r < 4; r++) acc[mi][ni][r] = 0.f;

    auto load_stage = [&](int s, int kt) {
#pragma unroll
        for (int i = 0; i < BM * 8 / 256; i++) {
            int idx = tid + i * 256;
            int row = idx >> 3, c4 = idx & 7;
            cp16(smA_u + (uint32_t)(s * BM * SK + row * SK + c4 * 4) * 4,
                 Ap + (size_t)(m0 + row) * K + kt + c4 * 4, true);
        }
#pragma unroll
        for (int i = 0; i < BN * 8 / 256; i++) {
            int idx = tid + i * 256;
            int row = idx >> 3, c4 = idx & 7;
            cp16(smW_u + (uint32_t)(s * BN * SK + row * SK + c4 * 4) * 4,
                 Wp + (size_t)(n0 + row) * K + kt + c4 * 4, (n0 + row) < Nw);
        }
        asm volatile("cp.async.commit_group;");
    };

    const int nk = K / 32;
    load_stage(0, 0);

    for (int kt = 0; kt < nk; kt++) {
        if (kt + 1 < nk) {
            load_stage((kt + 1) & 1, (kt + 1) * 32);
            asm volatile("cp.async.wait_group 1;");
        } else {
            asm volatile("cp.async.wait_group 0;");
        }
        __syncthreads();

        const float* sA = smA + (kt & 1) * BM * SK;
        const float* sW = smW + (kt & 1) * BN * SK;

#pragma unroll
        for (int k8 = 0; k8 < 4; k8++) {
            const int kb = k8 * 8 + lk;

            if (!x3) {
                uint32_t ua[MT][4], ub[NT][2];
#pragma unroll
                for (int mi = 0; mi < MT; mi++) {
                    int r = wm0 + mi * 16 + gr;
                    ua[mi][0] = __float_as_uint(sA[r * SK + kb]);
                    ua[mi][1] = __float_as_uint(sA[(r + 8) * SK + kb]);
                    ua[mi][2] = __float_as_uint(sA[r * SK + kb + 4]);
                    ua[mi][3] = __float_as_uint(sA[(r + 8) * SK + kb + 4]);
                }
#pragma unroll
                for (int ni = 0; ni < NT; ni++) {
                    int n = wn0 + ni * 8 + gr;
                    ub[ni][0] = __float_as_uint(sW[n * SK + kb]);
                    ub[ni][1] = __float_as_uint(sW[n * SK + kb + 4]);
                }
#pragma unroll
                for (int mi = 0; mi < MT; mi++)
#pragma unroll
                    for (int ni = 0; ni < NT; ni++)
                        mma8(acc[mi][ni], ua[mi], ub[ni]);
            } else {
                float ar[MT][4];
#pragma unroll
                for (int mi = 0; mi < MT; mi++) {
                    int r = wm0 + mi * 16 + gr;
                    ar[mi][0] = sA[r * SK + kb];
                    ar[mi][1] = sA[(r + 8) * SK + kb];
                    ar[mi][2] = sA[r * SK + kb + 4];
                    ar[mi][3] = sA[(r + 8) * SK + kb + 4];
                }
                float brr[NT][2];
#pragma unroll
                for (int ni = 0; ni < NT; ni++) {
                    int n = wn0 + ni * 8 + gr;
                    brr[ni][0] = sW[n * SK + kb];
                    brr[ni][1] = sW[n * SK + kb + 4];
                }
                uint32_t ubh[NT][2], ubl[NT][2];
#pragma unroll
                for (int ni = 0; ni < NT; ni++) {
#pragma unroll
                    for (int j = 0; j < 2; j++) {
                        uint32_t hh = f2tf(brr[ni][j]);
                        ubh[ni][j] = hh;
                        ubl[ni][j] = f2tf(brr[ni][j] - __uint_as_float(hh));
                    }
                }
#pragma unroll
                for (int mi = 0; mi < MT; mi++) {
                    uint32_t uah[4], ual[4];
#pragma unroll
                    for (int r = 0; r < 4; r++) {
                        uint32_t hh = f2tf(ar[mi][r]);
                        uah[r] = hh;
                        ual[r] = f2tf(ar[mi][r] - __uint_as_float(hh));
                    }
#pragma unroll
                    for (int ni = 0; ni < NT; ni++) {
                        mma8(acc[mi][ni], ual, ubh[ni]);
                        mma8(acc[mi][ni], uah, ubl[ni]);
                        mma8(acc[mi][ni], uah, ubh[ni]);
                    }
                }
            }
        }
        __syncthreads();
    }

#pragma unroll
    for (int mi = 0; mi < MT; mi++) {
        int row = m0 + wm0 + mi * 16 + gr;
#pragma unroll
        for (int ni = 0; ni < NT; ni++) {
            int col = n0 + wn0 + ni * 8 + lk * 2;
            if (col < Nv) {
                *(float2*)(Cout + (size_t)row * Nstride + col) =
                    make_float2(acc[mi][ni][0], acc[mi][ni][1]);
                *(float2*)(Cout + (size_t)(row + 8) * Nstride + col) =
                    make_float2(acc[mi][ni][2], acc[mi][ni][3]);
            }
        }
    }
}

// ---------------------------------------------------------------------------
// Fused conv+SiLU + dt/ldA prep — 2D grid, no per-thread div/mod on the
// conv path. blockIdx.x in [0,13): 128-channel strip; blockIdx.y: 4-row
// group (256 groups). blockIdx.x == 13: dt/ldA tail.
// Output xbc is TF32-ROUNDED so downstream mma fragments need no cvt.
// ---------------------------------------------------------------------------
__global__ __launch_bounds__(128) void conv_dt_kernel(
    const float* __restrict__ zx, const float* __restrict__ cw,
    const float* __restrict__ cb, const float* __restrict__ dt_bias,
    const float* __restrict__ A_log, float* __restrict__ out,
    float* __restrict__ dt_out, float* __restrict__ ldA_out)
{
    const int tid = threadIdx.x;
    if (blockIdx.x < 13) {
        const int c  = blockIdx.x * 128 + tid;          // channel 0..1663
        const int q  = blockIdx.y;                      // row group 0..255
        const int b  = q >> 7;                          // /(LL/4)
        const int l0 = (q & 127) * 4;

        float w0 = cw[c * 4 + 0], w1 = cw[c * 4 + 1];
        float w2 = cw[c * 4 + 2], w3 = cw[c * 4 + 3];
        float bias = cb[c];

        float v[7];
#pragma unroll
        for (int j = 0; j < 7; j++) {
            int t = l0 - 3 + j;
            v[j] = (t >= 0) ? zx[(size_t)(b * LL + t) * D_IN_PROJ + D_SSM + c] : 0.f;
        }
#pragma unroll
        for (int r = 0; r < 4; r++) {
            float sum = bias;
            sum = fmaf(v[r],     w0, sum);
            sum = fmaf(v[r + 1], w1, sum);
            sum = fmaf(v[r + 2], w2, sum);
            sum = fmaf(v[r + 3], w3, sum);
            float sig = 1.f / (1.f + expf(-sum));
            out[(size_t)(b * LL + l0 + r) * CONV_DIM + c] = tfr(sum * sig);
        }
    } else {
        int i2 = blockIdx.y * 128 + tid;                // 0..32767
        if (i2 < BL * NHEADS) {
            int h  = i2 % NHEADS;
            int bl = i2 / NHEADS;
            float raw = zx[(size_t)bl * D_IN_PROJ + DT_OFF + h] + dt_bias[h];
            float sp = fmaxf(raw, 0.f) + log1pf(expf(-fabsf(raw)));
            float dt = fminf(fmaxf(sp, 1e-6f), 1000.f);
            float A  = -expf(A_log[h]);
            dt_out[i2]  = dt;
            ldA_out[i2] = fmaxf(dt * A, LOG1EM6);
        }
    }
}

// ---------------------------------------------------------------------------
// Chunk kernel — tf32 tensor-core; inputs pre-rounded, no cvt in hot loops
// (except GEMM3's A-fragment which is an fp32 product).
// ---------------------------------------------------------------------------
__global__ __launch_bounds__(256) void chunk_kernel(
    const float* __restrict__ xbc, const float* __restrict__ dtb,
    const float* __restrict__ lda, float* __restrict__ yintra,
    float* __restrict__ Tg, float* __restrict__ aig,
    float* __restrict__ laendg)
{
    extern __shared__ float sm[];
    float* sX  = sm;             // [64][65]  tf32 values
    float* sB  = sm + 4160;      // tf32 values
    float* sC  = sm + 8320;      // C (tf32) then G (rounded at write)
    float* sdt = sm + 12480;
    float* sla = sdt + 64;
    float* sw  = sla + 64;

    const int bhc = blockIdx.x;
    const int c = bhc & (NCHUNK - 1);
    const int h = (bhc >> 3) % NHEADS;
    const int b = bhc / (NCHUNK * NHEADS);
    const int tid  = threadIdx.x;
    const int lane = tid & 31;
    const int warp = tid >> 5;
    const int gr   = lane >> 2;
    const int lk   = lane & 3;
    const int wm0  = (warp & 1) * 32;
    const int wn0  = (warp >> 1) * 16;
    const int row0 = b * LL + c * QC;

#pragma unroll
    for (int idx = tid; idx < 64 * 16; idx += 256) {
        int i = idx >> 4, f = idx & 15;
        const float* rp = xbc + (size_t)(row0 + i) * CONV_DIM;
        float4 xv = *(const float4*)(rp + h * HEADDIM + f * 4);
        float4 bv = *(const float4*)(rp + D_SSM + f * 4);
        float4 cv = *(const float4*)(rp + D_SSM + D_STATE + f * 4);
        float* xr = sX + i * 65 + f * 4;
        xr[0] = xv.x; xr[1] = xv.y; xr[2] = xv.z; xr[3] = xv.w;
        float* br = sB + i * 65 + f * 4;
        br[0] = bv.x; br[1] = bv.y; br[2] = bv.z; br[3] = bv.w;
        float* cr = sC + i * 65 + f * 4;
        cr[0] = cv.x; cr[1] = cv.y; cr[2] = cv.z; cr[3] = cv.w;
    }
    if (tid < 64) {
        sdt[tid] = dtb[(row0 + tid) * NHEADS + h];
        sla[tid] = lda[(row0 + tid) * NHEADS + h];
    }
    __syncthreads();
    if (tid < 32) {
        float a = sla[tid];
#pragma unroll
        for (int o = 1; o < 32; o <<= 1) {
            float n = __shfl_up_sync(0xffffffffu, a, o);
            if (lane >= o) a += n;
        }
        float tot = __shfl_sync(0xffffffffu, a, 31);
        float bb2 = sla[32 + tid];
#pragma unroll
        for (int o = 1; o < 32; o <<= 1) {
            float n = __shfl_up_sync(0xffffffffu, bb2, o);
            if (lane >= o) bb2 += n;
        }
        sla[tid] = a;
        sla[32 + tid] = bb2 + tot;
    }
    __syncthreads();
    if (tid < 64) {
        sw[tid] = expf(sla[63] - sla[tid]) * sdt[tid];
        aig[bhc * QC + tid] = expf(sla[tid]);
        if (tid == 0) laendg[bhc] = sla[63];
    }

    // --- GEMM1: CB[i][j] = sum_n C[i,n] * B[j,n]  (operands pre-rounded) ---
    float acc1[2][2][4];
#pragma unroll
    for (int mi = 0; mi < 2; mi++)
#pragma unroll
        for (int ni = 0; ni < 2; ni++)
#pragma unroll
            for (int e = 0; e < 4; e++) acc1[mi][ni][e] = 0.f;

#pragma unroll
    for (int k8 = 0; k8 < 8; k8++) {
        int kb = k8 * 8 + lk;
        uint32_t ua[2][4], ub[2][2];
#pragma unroll
        for (int mi = 0; mi < 2; mi++) {
            int r = wm0 + mi * 16 + gr;
            ua[mi][0] = __float_as_uint(sC[r * 65 + kb]);
            ua[mi][1] = __float_as_uint(sC[(r + 8) * 65 + kb]);
            ua[mi][2] = __float_as_uint(sC[r * 65 + kb + 4]);
            ua[mi][3] = __float_as_uint(sC[(r + 8) * 65 + kb + 4]);
        }
#pragma unroll
        for (int ni = 0; ni < 2; ni++) {
            int j = wn0 + ni * 8 + gr;
            ub[ni][0] = __float_as_uint(sB[j * 65 + kb]);
            ub[ni][1] = __float_as_uint(sB[j * 65 + kb + 4]);
        }
#pragma unroll
        for (int mi = 0; mi < 2; mi++)
#pragma unroll
            for (int ni = 0; ni < 2; ni++)
                mma8(acc1[mi][ni], ua[mi], ub[ni]);
    }
    __syncthreads();

    // mask + scale into G (tf32-rounded at write; overwrites sC)
#pragma unroll
    for (int mi = 0; mi < 2; mi++) {
        int ilo = wm0 + mi * 16 + gr;
        int ihi = ilo + 8;
#pragma unroll
        for (int ni = 0; ni < 2; ni++) {
            int j0c = wn0 + ni * 8 + 2 * lk;
            int j1c = j0c + 1;
            float g00 = (j0c <= ilo) ? acc1[mi][ni][0] * sdt[j0c] * expf(sla[ilo] - sla[j0c]) : 0.f;
            float g01 = (j1c <= ilo) ? acc1[mi][ni][1] * sdt[j1c] * expf(sla[ilo] - sla[j1c]) : 0.f;
            float g10 = (j0c <= ihi) ? acc1[mi][ni][2] * sdt[j0c] * expf(sla[ihi] - sla[j0c]) : 0.f;
            float g11 = (j1c <= ihi) ? acc1[mi][ni][3] * sdt[j1c] * expf(sla[ihi] - sla[j1c]) : 0.f;
            sC[ilo * 65 + j0c] = tfr(g00);
            sC[ilo * 65 + j1c] = tfr(g01);
            sC[ihi * 65 + j0c] = tfr(g10);
            sC[ihi * 65 + j1c] = tfr(g11);
        }
    }
    __syncthreads();

    // --- GEMM2: Y[i][p] = sum_j G[i,j] * X[j,p]  (both pre-rounded) ---
    {
        float acc2[2][2][4];
#pragma unroll
        for (int mi = 0; mi < 2; mi++)
#pragma unroll
            for (int ni = 0; ni < 2; ni++)
#pragma unroll
                for (int e = 0; e < 4; e++) acc2[mi][ni][e] = 0.f;

#pragma unroll
        for (int k8 = 0; k8 < 8; k8++) {
            int kb = k8 * 8 + lk;
            uint32_t ua[2][4], ub[2][2];
#pragma unroll
            for (int mi = 0; mi < 2; mi++) {
                int r = wm0 + mi * 16 + gr;
                ua[mi][0] = __float_as_uint(sC[r * 65 + kb]);
                ua[mi][1] = __float_as_uint(sC[(r + 8) * 65 + kb]);
                ua[mi][2] = __float_as_uint(sC[r * 65 + kb + 4]);
                ua[mi][3] = __float_as_uint(sC[(r + 8) * 65 + kb + 4]);
            }
#pragma unroll
            for (int ni = 0; ni < 2; ni++) {
                int p = wn0 + ni * 8 + gr;
                ub[ni][0] = __float_as_uint(sX[kb * 65 + p]);
                ub[ni][1] = __float_as_uint(sX[(kb + 4) * 65 + p]);
            }
#pragma unroll
            for (int mi = 0; mi < 2; mi++)
#pragma unroll
                for (int ni = 0; ni < 2; ni++)
                    mma8(acc2[mi][ni], ua[mi], ub[ni]);
        }
#pragma unroll
        for (int mi = 0; mi < 2; mi++) {
            int ilo = wm0 + mi * 16 + gr;
#pragma unroll
            for (int ni = 0; ni < 2; ni++) {
                int pc = wn0 + ni * 8 + 2 * lk;
                *(float2*)(yintra + (size_t)(row0 + ilo) * D_SSM + h * HEADDIM + pc) =
                    make_float2(acc2[mi][ni][0], acc2[mi][ni][1]);
                *(float2*)(yintra + (size_t)(row0 + ilo + 8) * D_SSM + h * HEADDIM + pc) =
                    make_float2(acc2[mi][ni][2], acc2[mi][ni][3]);
            }
        }
    }

    // --- GEMM3: T[p][n] = sum_j (w_j * X[j,p]) * B[j,n] ---
    {
        float acc3[2][2][4];
#pragma unroll
        for (int mi = 0; mi < 2; mi++)
#pragma unroll
            for (int ni = 0; ni < 2; ni++)
#pragma unroll
                for (int e = 0; e < 4; e++) acc3[mi][ni][e] = 0.f;

#pragma unroll
        for (int k8 = 0; k8 < 8; k8++) {
            int kb = k8 * 8 + lk;
            float w0 = sw[kb], w1 = sw[kb + 4];
            uint32_t ua[2][4], ub[2][2];
#pragma unroll
            for (int mi = 0; mi < 2; mi++) {
                int r = wm0 + mi * 16 + gr;   // p index
                ua[mi][0] = f2tf(sX[kb * 65 + r] * w0);
                ua[mi][1] = f2tf(sX[kb * 65 + r + 8] * w0);
                ua[mi][2] = f2tf(sX[(kb + 4) * 65 + r] * w1);
                ua[mi][3] = f2tf(sX[(kb + 4) * 65 + r + 8] * w1);
            }
#pragma unroll
            for (int ni = 0; ni < 2; ni++) {
                int n = wn0 + ni * 8 + gr;
                ub[ni][0] = __float_as_uint(sB[kb * 65 + n]);
                ub[ni][1] = __float_as_uint(sB[(kb + 4) * 65 + n]);
            }
#pragma unroll
            for (int mi = 0; mi < 2; mi++)
#pragma unroll
                for (int ni = 0; ni < 2; ni++)
                    mma8(acc3[mi][ni], ua[mi], ub[ni]);
        }
#pragma unroll
        for (int mi = 0; mi < 2; mi++) {
            int plo = wm0 + mi * 16 + gr;
#pragma unroll
            for (int ni = 0; ni < 2; ni++) {
                int nc = wn0 + ni * 8 + 2 * lk;
                *(float2*)(Tg + (size_t)bhc * 4096 + plo * 64 + nc) =
                    make_float2(acc3[mi][ni][0], acc3[mi][ni][1]);
                *(float2*)(Tg + (size_t)bhc * 4096 + (plo + 8) * 64 + nc) =
                    make_float2(acc3[mi][ni][2], acc3[mi][ni][3]);
            }
        }
    }
}

// ---------------------------------------------------------------------------
// Parallel chunk-state combine: 768 blocks; Sg written tf32-rounded.
// ---------------------------------------------------------------------------
__global__ __launch_bounds__(256) void combine_kernel(
    const float* __restrict__ Tg, const float* __restrict__ laendg,
    float* __restrict__ Sg)
{
    const int bh  = blockIdx.x >> 4;
    const int e   = (blockIdx.x & 15) * 256 + threadIdx.x;
    float s = 0.f;
#pragma unroll
    for (int c = 0; c < NCHUNK; c++) {
        int bhc = bh * NCHUNK + c;
        Sg[(size_t)bhc * 4096 + e] = tfr(s);
        float ae = expf(__ldg(laendg + bhc));
        s = fmaf(ae, s, Tg[(size_t)bhc * 4096 + e]);
    }
}

// ---------------------------------------------------------------------------
// Inter-chunk contribution + skip + gating — tf32 mma; operands pre-rounded;
// writes y rounded to tf32 for out_proj.
// ---------------------------------------------------------------------------
__global__ __launch_bounds__(256) void inter_kernel(
    const float* __restrict__ xbc, const float* __restrict__ Sg,
    const float* __restrict__ aig, const float* __restrict__ zx,
    const float* __restrict__ Dp, float* __restrict__ y)
{
    __shared__ float sC[64 * 65];
    __shared__ float sS[64 * 65];
    __shared__ float sai[64];

    const int bhc = blockIdx.x;
    const int c = bhc & (NCHUNK - 1);
    const int h = (bhc >> 3) % NHEADS;
    const int b = bhc / (NCHUNK * NHEADS);
    const int tid  = threadIdx.x;
    const int lane = tid & 31;
    const int warp = tid >> 5;
    const int gr   = lane >> 2;
    const int lk   = lane & 3;
    const int wm0  = (warp & 1) * 32;
    const int wn0  = (warp >> 1) * 16;
    const int row0 = b * LL + c * QC;

#pragma unroll
    for (int idx = tid; idx < 64 * 16; idx += 256) {
        int i = idx >> 4, f = idx & 15;
        const float* rp = xbc + (size_t)(row0 + i) * CONV_DIM;
        float4 cv = *(const float4*)(rp + D_SSM + D_STATE + f * 4);
        float* cr = sC + i * 65 + f * 4;
        cr[0] = cv.x; cr[1] = cv.y; cr[2] = cv.z; cr[3] = cv.w;
        float4 sv = *(const float4*)(Sg + (size_t)bhc * 4096 + i * 64 + f * 4);
        float* sr = sS + i * 65 + f * 4;
        sr[0] = sv.x; sr[1] = sv.y; sr[2] = sv.z; sr[3] = sv.w;
    }
    if (tid < 64) sai[tid] = aig[bhc * QC + tid];
    __syncthreads();

    float acc[2][2][4];
#pragma unroll
    for (int mi = 0; mi < 2; mi++)
#pragma unroll
        for (int ni = 0; ni < 2; ni++)
#pragma unroll
            for (int e = 0; e < 4; e++) acc[mi][ni][e] = 0.f;

#pragma unroll
    for (int k8 = 0; k8 < 8; k8++) {
        int kb = k8 * 8 + lk;
        uint32_t ua[2][4], ub[2][2];
#pragma unroll
        for (int mi = 0; mi < 2; mi++) {
            int r = wm0 + mi * 16 + gr;
            ua[mi][0] = __float_as_uint(sC[r * 65 + kb]);
            ua[mi][1] = __float_as_uint(sC[(r + 8) * 65 + kb]);
            ua[mi][2] = __float_as_uint(sC[r * 65 + kb + 4]);
            ua[mi][3] = __float_as_uint(sC[(r + 8) * 65 + kb + 4]);
        }
#pragma unroll
        for (int ni = 0; ni < 2; ni++) {
            int p = wn0 + ni * 8 + gr;
            ub[ni][0] = __float_as_uint(sS[p * 65 + kb]);
            ub[ni][1] = __float_as_uint(sS[p * 65 + kb + 4]);
        }
#pragma unroll
        for (int mi = 0; mi < 2; mi++)
#pragma unroll
            for (int ni = 0; ni < 2; ni++)
                mma8(acc[mi][ni], ua[mi], ub[ni]);
    }

    const float Dv = Dp[h];
#pragma unroll
    for (int mi = 0; mi < 2; mi++) {
        int rows[2] = { wm0 + mi * 16 + gr, wm0 + mi * 16 + gr + 8 };
#pragma unroll
        for (int rr = 0; rr < 2; rr++) {
            int i = rows[rr];
            size_t r = row0 + i;
            float aiv = sai[i];
#pragma unroll
            for (int ni = 0; ni < 2; ni++) {
                int pc = wn0 + ni * 8 + 2 * lk;
                float a0 = acc[mi][ni][rr * 2 + 0];
                float a1 = acc[mi][ni][rr * 2 + 1];
                float2 xv = *(const float2*)(xbc + r * CONV_DIM + h * HEADDIM + pc);
                float2 zv = *(const float2*)(zx + r * D_IN_PROJ + h * HEADDIM + pc);
                float2 yv = *(float2*)(y + r * D_SSM + h * HEADDIM + pc);
                float y0 = yv.x + aiv * a0 + Dv * xv.x;
                float y1 = yv.y + aiv * a1 + Dv * xv.y;
                y0 *= zv.x * (1.f / (1.f + expf(-zv.x)));
                y1 *= zv.y * (1.f / (1.f + expf(-zv.y)));
                *(float2*)(y + r * D_SSM + h * HEADDIM + pc) =
                    make_float2(tfr(y0), tfr(y1));
            }
        }
    }
}

// ---------------------------------------------------------------------------
// Launch — single-stream R12 pipeline
// ---------------------------------------------------------------------------
extern "C" void kernel_launch(void* const* d_in, const int* in_sizes, int n_in,
                              void* d_out, int out_size)
{
    const float* u       = (const float*)d_in[0];
    const float* W_in    = (const float*)d_in[1];
    const float* conv_w  = (const float*)d_in[2];
    const float* conv_b  = (const float*)d_in[3];
    const float* dt_bias = (const float*)d_in[4];
    const float* A_log   = (const float*)d_in[5];
    const float* D_param = (const float*)d_in[6];
    const float* W_out   = (const float*)d_in[7];
    float* out = (float*)d_out;

    float *zx, *xbc, *dt, *ldA, *y, *Tg, *Sg, *aig, *laendg, *uc, *Wic, *Woc;
    cudaGetSymbolAddress((void**)&zx,     g_zxbcdt);
    cudaGetSymbolAddress((void**)&xbc,    g_xbc);
    cudaGetSymbolAddress((void**)&dt,     g_dt);
    cudaGetSymbolAddress((void**)&ldA,    g_ldA);
    cudaGetSymbolAddress((void**)&y,      g_y);
    cudaGetSymbolAddress((void**)&Tg,     g_T);
    cudaGetSymbolAddress((void**)&Sg,     g_S);
    cudaGetSymbolAddress((void**)&aig,    g_ai);
    cudaGetSymbolAddress((void**)&laendg, g_laend);
    cudaGetSymbolAddress((void**)&uc,     g_uc);
    cudaGetSymbolAddress((void**)&Wic,    g_Wic);
    cudaGetSymbolAddress((void**)&Woc,    g_Woc);

    static bool attr_done = false;
    if (!attr_done) {
        cudaFuncSetAttribute(chunk_kernel,
                             cudaFuncAttributeMaxDynamicSharedMemorySize, 51200);
        cudaFuncSetAttribute(mma_gemm<64, 128>,
                             cudaFuncAttributeMaxDynamicSharedMemorySize, 55296);
        cudaFuncSetAttribute(mma_gemm<64, 64>,
                             cudaFuncAttributeMaxDynamicSharedMemorySize, 36864);
        attr_done = true;
    }

    // 0) tf32 pre-round of u, W_in, W_out
    {
        int n4 = (UN_F + WIN_F + WOUT_F) / 4;
        tf32_prep_kernel<<<(n4 + 255) / 256, 256>>>(
            (const float4*)u, (const float4*)W_in, (const float4*)W_out,
            (float4*)uc, (float4*)Wic, (float4*)Woc);
    }

    // 1) in_proj: 64x128 tiles, 416 blocks; pre-rounded 1x except
    //    B/C block-col [3072,3200) tf32x3 (raw)
    {
        dim3 grid(26, BL / 64);
        mma_gemm<64, 128><<<grid, 256, 55296>>>(
            uc, u, Wic, W_in, zx, D_IN_PROJ, D_IN_PROJ, D_IN_PROJ, D_MODEL,
            3072, 3200);
    }
    // 2) conv + silu + dt/ldA (2D grid, div-free conv path)
    {
        dim3 grid(14, 256);
        conv_dt_kernel<<<grid, 128>>>(
            zx, conv_w, conv_b, dt_bias, A_log, xbc, dt, ldA);
    }
    // 3) chunked scan
    chunk_kernel<<<NBHC, 256, 51200>>>(xbc, dt, ldA, y, Tg, aig, laendg);
    combine_kernel<<<BB * NHEADS * 16, 256>>>(Tg, laendg, Sg);
    inter_kernel<<<NBHC, 256>>>(xbc, Sg, aig, zx, D_param, y);

    // 4) out_proj: 64x64 tiles, 192 blocks
    {
        dim3 grid(D_MODEL / 64, BL / 64);
        mma_gemm<64, 64><<<grid, 256, 36864>>>(
            y, y, Woc, W_out, out, D_MODEL, D_MODEL, D_MODEL, D_SSM,
            1 << 30, 1 << 30);
    }
}

// round 17
// speedup vs baseline: 1.1818x; 1.0891x over previous
#include <cuda_runtime.h>
#include <cuda_bf16.h>
#include <math.h>
#include <stdint.h>

// ---------------------------------------------------------------------------
// Problem dimensions (compile-time)
// ---------------------------------------------------------------------------
#define D_MODEL   768
#define D_STATE   64
#define D_CONV    4
#define D_SSM     1536
#define HEADDIM   64
#define NHEADS    24
#define CONV_DIM  1664
#define D_IN_PROJ 3224
#define BB        2
#define LL        512
#define BL        (BB*LL)
#define QC        64
#define NCHUNK    (LL/QC)
#define NBHC      (BB*NHEADS*NCHUNK)

#define DT_OFF    (D_SSM + CONV_DIM)
#define LOG1EM6   (-13.815510558f)

#define SKP       68                    // padded smem row stride (floats)
#define TILE_F    (64*SKP)              // 4352 floats per 64x64 tile

#define UN_F      (BL * D_MODEL)        // 786432
#define WIN_F     (D_IN_PROJ * D_MODEL) // 2476032
#define WOUT_F    (D_MODEL * D_SSM)     // 1179648

// ---------------------------------------------------------------------------
// Scratch (static device globals)
// ---------------------------------------------------------------------------
__device__ float g_zxbcdt[BL * D_IN_PROJ];
__device__ float g_xbc[BL * CONV_DIM];      // tf32-rounded conv output
__device__ float g_dt[BL * NHEADS];
__device__ float g_ldA[BL * NHEADS];
__device__ float g_y[BL * D_SSM];           // tf32-rounded gated output
__device__ float g_T[NBHC * HEADDIM * D_STATE];
__device__ float g_S[NBHC * HEADDIM * D_STATE]; // tf32-rounded chunk states
__device__ float g_ai[NBHC * QC];
__device__ float g_laend[NBHC];
__device__ float g_uc[UN_F];                // tf32-rounded u
__device__ float g_Wic[WIN_F];              // tf32-rounded W_in
__device__ float g_Woc[WOUT_F];             // tf32-rounded W_out

// ---------------------------------------------------------------------------
// TF32 helpers
// ---------------------------------------------------------------------------
__device__ __forceinline__ uint32_t f2tf(float x) {
    uint32_t r;
    asm("cvt.rna.tf32.f32 %0, %1;" : "=r"(r) : "f"(x));
    return r;
}
__device__ __forceinline__ float tfr(float x) {
    return __uint_as_float(f2tf(x));
}

__device__ __forceinline__ void mma8(float* d, const uint32_t* a, const uint32_t* b) {
    asm volatile(
        "mma.sync.aligned.m16n8k8.row.col.f32.tf32.tf32.f32 "
        "{%0,%1,%2,%3},{%4,%5,%6,%7},{%8,%9},{%0,%1,%2,%3};"
        : "+f"(d[0]), "+f"(d[1]), "+f"(d[2]), "+f"(d[3])
        : "r"(a[0]), "r"(a[1]), "r"(a[2]), "r"(a[3]), "r"(b[0]), "r"(b[1]));
}

__device__ __forceinline__ void cp16(uint32_t dst, const void* src, bool pred) {
    int bytes = pred ? 16 : 0;
    asm volatile("cp.async.cg.shared.global [%0], [%1], 16, %2;\n"
                 :: "r"(dst), "l"(src), "r"(bytes));
}

// ---------------------------------------------------------------------------
// tf32 pre-round: u, W_in, W_out  ->  g_uc, g_Wic, g_Woc  (float4 stream)
// ---------------------------------------------------------------------------
__global__ void tf32_prep_kernel(const float4* __restrict__ u,
                                 const float4* __restrict__ Wi,
                                 const float4* __restrict__ Wo,
                                 float4* __restrict__ uc,
                                 float4* __restrict__ Wic,
                                 float4* __restrict__ Woc)
{
    int i = blockIdx.x * blockDim.x + threadIdx.x;
    const int n0 = UN_F / 4, n1 = WIN_F / 4, n2 = WOUT_F / 4;
    float4 v; float4* dst;
    if (i < n0)                { v = u[i];            dst = uc + i; }
    else if (i < n0 + n1)      { v = Wi[i - n0];      dst = Wic + (i - n0); }
    else if (i < n0 + n1 + n2) { v = Wo[i - n0 - n1]; dst = Woc + (i - n0 - n1); }
    else return;
    v.x = tfr(v.x); v.y = tfr(v.y); v.z = tfr(v.z); v.w = tfr(v.w);
    *dst = v;
}

// ---------------------------------------------------------------------------
// TF32 MMA GEMM:  C[m, n] = sum_k A[m,k] * W[n,k]
// 2-stage cp.async, 256 threads, warp grid 2(m) x 4(n).
// 1x block-cols: pre-rounded operands, scalar LDS fragments (no cvt);
// x3 block-cols (n0 in [x3col0,x3col1)): RAW staging + tf32x3 hi/lo.
// ---------------------------------------------------------------------------
template<int BM, int BN>
__global__ __launch_bounds__(256, 4) void mma_gemm(
    const float* __restrict__ Acv, const float* __restrict__ Araw,
    const float* __restrict__ Wcv, const float* __restrict__ Wraw,
    float* __restrict__ Cout, int Nw, int Nv, int Nstride, int K,
    int x3col0, int x3col1)
{
    constexpr int MT = BM / 32;
    constexpr int NT = BN / 32;
    constexpr int SK = 36;

    extern __shared__ float sm_f[];
    float* smA = sm_f;                   // [2][BM][SK]
    float* smW = sm_f + 2 * BM * SK;     // [2][BN][SK]

    const int tid  = threadIdx.x;
    const int lane = tid & 31;
    const int warp = tid >> 5;
    const int wm0  = (warp & 1) * (BM / 2);
    const int wn0  = (warp >> 1) * (BN / 4);
    const int m0   = blockIdx.y * BM;
    const int n0   = blockIdx.x * BN;
    const bool x3  = (n0 >= x3col0) && (n0 < x3col1);
    const int gr   = lane >> 2;
    const int lk   = lane & 3;

    const float* Ap = x3 ? Araw : Acv;
    const float* Wp = x3 ? Wraw : Wcv;

    uint32_t smA_u = (uint32_t)__cvta_generic_to_shared(smA);
    uint32_t smW_u = (uint32_t)__cvta_generic_to_shared(smW);

    float acc[MT][NT][4];
#pragma unroll
    for (int mi = 0; mi < MT; mi++)
#pragma unroll
        for (int ni = 0; ni < NT; ni++)
#pragma unroll
            for (int r = 0; r < 4; r++) acc[mi][ni][r] = 0.f;

    auto load_stage = [&](int s, int kt) {
#pragma unroll
        for (int i = 0; i < BM * 8 / 256; i++) {
            int idx = tid + i * 256;
            int row = idx >> 3, c4 = idx & 7;
            cp16(smA_u + (uint32_t)(s * BM * SK + row * SK + c4 * 4) * 4,
                 Ap + (size_t)(m0 + row) * K + kt + c4 * 4, true);
        }
#pragma unroll
        for (int i = 0; i < BN * 8 / 256; i++) {
            int idx = tid + i * 256;
            int row = idx >> 3, c4 = idx & 7;
            cp16(smW_u + (uint32_t)(s * BN * SK + row * SK + c4 * 4) * 4,
                 Wp + (size_t)(n0 + row) * K + kt + c4 * 4, (n0 + row) < Nw);
        }
        asm volatile("cp.async.commit_group;");
    };

    const int nk = K / 32;
    load_stage(0, 0);

    for (int kt = 0; kt < nk; kt++) {
        if (kt + 1 < nk) {
            load_stage((kt + 1) & 1, (kt + 1) * 32);
            asm volatile("cp.async.wait_group 1;");
        } else {
            asm volatile("cp.async.wait_group 0;");
        }
        __syncthreads();

        const float* sA = smA + (kt & 1) * BM * SK;
        const float* sW = smW + (kt & 1) * BN * SK;

#pragma unroll
        for (int k8 = 0; k8 < 4; k8++) {
            const int kb = k8 * 8 + lk;

            if (!x3) {
                uint32_t ua[MT][4], ub[NT][2];
#pragma unroll
                for (int mi = 0; mi < MT; mi++) {
                    int r = wm0 + mi * 16 + gr;
                    ua[mi][0] = __float_as_uint(sA[r * SK + kb]);
                    ua[mi][1] = __float_as_uint(sA[(r + 8) * SK + kb]);
                    ua[mi][2] = __float_as_uint(sA[r * SK + kb + 4]);
                    ua[mi][3] = __float_as_uint(sA[(r + 8) * SK + kb + 4]);
                }
#pragma unroll
                for (int ni = 0; ni < NT; ni++) {
                    int n = wn0 + ni * 8 + gr;
                    ub[ni][0] = __float_as_uint(sW[n * SK + kb]);
                    ub[ni][1] = __float_as_uint(sW[n * SK + kb + 4]);
                }
#pragma unroll
                for (int mi = 0; mi < MT; mi++)
#pragma unroll
                    for (int ni = 0; ni < NT; ni++)
                        mma8(acc[mi][ni], ua[mi], ub[ni]);
            } else {
                float ar[MT][4];
#pragma unroll
                for (int mi = 0; mi < MT; mi++) {
                    int r = wm0 + mi * 16 + gr;
                    ar[mi][0] = sA[r * SK + kb];
                    ar[mi][1] = sA[(r + 8) * SK + kb];
                    ar[mi][2] = sA[r * SK + kb + 4];
                    ar[mi][3] = sA[(r + 8) * SK + kb + 4];
                }
                float brr[NT][2];
#pragma unroll
                for (int ni = 0; ni < NT; ni++) {
                    int n = wn0 + ni * 8 + gr;
                    brr[ni][0] = sW[n * SK + kb];
                    brr[ni][1] = sW[n * SK + kb + 4];
                }
                uint32_t ubh[NT][2], ubl[NT][2];
#pragma unroll
                for (int ni = 0; ni < NT; ni++) {
#pragma unroll
                    for (int j = 0; j < 2; j++) {
                        uint32_t hh = f2tf(brr[ni][j]);
                        ubh[ni][j] = hh;
                        ubl[ni][j] = f2tf(brr[ni][j] - __uint_as_float(hh));
                    }
                }
#pragma unroll
                for (int mi = 0; mi < MT; mi++) {
                    uint32_t uah[4], ual[4];
#pragma unroll
                    for (int r = 0; r < 4; r++) {
                        uint32_t hh = f2tf(ar[mi][r]);
                        uah[r] = hh;
                        ual[r] = f2tf(ar[mi][r] - __uint_as_float(hh));
                    }
#pragma unroll
                    for (int ni = 0; ni < NT; ni++) {
                        mma8(acc[mi][ni], ual, ubh[ni]);
                        mma8(acc[mi][ni], uah, ubl[ni]);
                        mma8(acc[mi][ni], uah, ubh[ni]);
                    }
                }
            }
        }
        __syncthreads();
    }

#pragma unroll
    for (int mi = 0; mi < MT; mi++) {
        int row = m0 + wm0 + mi * 16 + gr;
#pragma unroll
        for (int ni = 0; ni < NT; ni++) {
            int col = n0 + wn0 + ni * 8 + lk * 2;
            if (col < Nv) {
                *(float2*)(Cout + (size_t)row * Nstride + col) =
                    make_float2(acc[mi][ni][0], acc[mi][ni][1]);
                *(float2*)(Cout + (size_t)(row + 8) * Nstride + col) =
                    make_float2(acc[mi][ni][2], acc[mi][ni][3]);
            }
        }
    }
}

// ---------------------------------------------------------------------------
// Fused conv+SiLU + dt/ldA prep — 2D grid, no per-thread div/mod on the
// conv path. Output xbc is TF32-ROUNDED.
// ---------------------------------------------------------------------------
__global__ __launch_bounds__(128) void conv_dt_kernel(
    const float* __restrict__ zx, const float* __restrict__ cw,
    const float* __restrict__ cb, const float* __restrict__ dt_bias,
    const float* __restrict__ A_log, float* __restrict__ out,
    float* __restrict__ dt_out, float* __restrict__ ldA_out)
{
    const int tid = threadIdx.x;
    if (blockIdx.x < 13) {
        const int c  = blockIdx.x * 128 + tid;          // channel 0..1663
        const int q  = blockIdx.y;                      // row group 0..255
        const int b  = q >> 7;
        const int l0 = (q & 127) * 4;

        float w0 = cw[c * 4 + 0], w1 = cw[c * 4 + 1];
        float w2 = cw[c * 4 + 2], w3 = cw[c * 4 + 3];
        float bias = cb[c];

        float v[7];
#pragma unroll
        for (int j = 0; j < 7; j++) {
            int t = l0 - 3 + j;
            v[j] = (t >= 0) ? zx[(size_t)(b * LL + t) * D_IN_PROJ + D_SSM + c] : 0.f;
        }
#pragma unroll
        for (int r = 0; r < 4; r++) {
            float sum = bias;
            sum = fmaf(v[r],     w0, sum);
            sum = fmaf(v[r + 1], w1, sum);
            sum = fmaf(v[r + 2], w2, sum);
            sum = fmaf(v[r + 3], w3, sum);
            float sig = 1.f / (1.f + expf(-sum));
            out[(size_t)(b * LL + l0 + r) * CONV_DIM + c] = tfr(sum * sig);
        }
    } else {
        int i2 = blockIdx.y * 128 + tid;
        if (i2 < BL * NHEADS) {
            int h  = i2 % NHEADS;
            int bl = i2 / NHEADS;
            float raw = zx[(size_t)bl * D_IN_PROJ + DT_OFF + h] + dt_bias[h];
            float sp = fmaxf(raw, 0.f) + log1pf(expf(-fabsf(raw)));
            float dt = fminf(fmaxf(sp, 1e-6f), 1000.f);
            float A  = -expf(A_log[h]);
            dt_out[i2]  = dt;
            ldA_out[i2] = fmaxf(dt * A, LOG1EM6);
        }
    }
}

// ---------------------------------------------------------------------------
// Chunk kernel — tf32 tensor-core; smem stride SKP=68 so staging uses
// aligned float4 stores (STS.128). Fragment loads stay conflict-free:
// bank(r*68+kb) = (4r+kb) mod 32, distinct across the 8 fragment rows.
// ---------------------------------------------------------------------------
__global__ __launch_bounds__(256) void chunk_kernel(
    const float* __restrict__ xbc, const float* __restrict__ dtb,
    const float* __restrict__ lda, float* __restrict__ yintra,
    float* __restrict__ Tg, float* __restrict__ aig,
    float* __restrict__ laendg)
{
    extern __shared__ float sm[];
    float* sX  = sm;                 // [64][SKP]  tf32 values
    float* sB  = sm + TILE_F;        // tf32 values
    float* sC  = sm + 2 * TILE_F;    // C (tf32) then G (rounded at write)
    float* sdt = sm + 3 * TILE_F;
    float* sla = sdt + 64;
    float* sw  = sla + 64;

    const int bhc = blockIdx.x;
    const int c = bhc & (NCHUNK - 1);
    const int h = (bhc >> 3) % NHEADS;
    const int b = bhc / (NCHUNK * NHEADS);
    const int tid  = threadIdx.x;
    const int lane = tid & 31;
    const int warp = tid >> 5;
    const int gr   = lane >> 2;
    const int lk   = lane & 3;
    const int wm0  = (warp & 1) * 32;
    const int wn0  = (warp >> 1) * 16;
    const int row0 = b * LL + c * QC;

#pragma unroll
    for (int idx = tid; idx < 64 * 16; idx += 256) {
        int i = idx >> 4, f = idx & 15;
        const float* rp = xbc + (size_t)(row0 + i) * CONV_DIM;
        float4 xv = *(const float4*)(rp + h * HEADDIM + f * 4);
        float4 bv = *(const float4*)(rp + D_SSM + f * 4);
        float4 cv = *(const float4*)(rp + D_SSM + D_STATE + f * 4);
        *(float4*)(sX + i * SKP + f * 4) = xv;
        *(float4*)(sB + i * SKP + f * 4) = bv;
        *(float4*)(sC + i * SKP + f * 4) = cv;
    }
    if (tid < 64) {
        sdt[tid] = dtb[(row0 + tid) * NHEADS + h];
        sla[tid] = lda[(row0 + tid) * NHEADS + h];
    }
    __syncthreads();
    if (tid < 32) {
        float a = sla[tid];
#pragma unroll
        for (int o = 1; o < 32; o <<= 1) {
            float n = __shfl_up_sync(0xffffffffu, a, o);
            if (lane >= o) a += n;
        }
        float tot = __shfl_sync(0xffffffffu, a, 31);
        float bb2 = sla[32 + tid];
#pragma unroll
        for (int o = 1; o < 32; o <<= 1) {
            float n = __shfl_up_sync(0xffffffffu, bb2, o);
            if (lane >= o) bb2 += n;
        }
        sla[tid] = a;
        sla[32 + tid] = bb2 + tot;
    }
    __syncthreads();
    if (tid < 64) {
        sw[tid] = expf(sla[63] - sla[tid]) * sdt[tid];
        aig[bhc * QC + tid] = expf(sla[tid]);
        if (tid == 0) laendg[bhc] = sla[63];
    }

    // --- GEMM1: CB[i][j] = sum_n C[i,n] * B[j,n]  (operands pre-rounded) ---
    float acc1[2][2][4];
#pragma unroll
    for (int mi = 0; mi < 2; mi++)
#pragma unroll
        for (int ni = 0; ni < 2; ni++)
#pragma unroll
            for (int e = 0; e < 4; e++) acc1[mi][ni][e] = 0.f;

#pragma unroll
    for (int k8 = 0; k8 < 8; k8++) {
        int kb = k8 * 8 + lk;
        uint32_t ua[2][4], ub[2][2];
#pragma unroll
        for (int mi = 0; mi < 2; mi++) {
            int r = wm0 + mi * 16 + gr;
            ua[mi][0] = __float_as_uint(sC[r * SKP + kb]);
            ua[mi][1] = __float_as_uint(sC[(r + 8) * SKP + kb]);
            ua[mi][2] = __float_as_uint(sC[r * SKP + kb + 4]);
            ua[mi][3] = __float_as_uint(sC[(r + 8) * SKP + kb + 4]);
        }
#pragma unroll
        for (int ni = 0; ni < 2; ni++) {
            int j = wn0 + ni * 8 + gr;
            ub[ni][0] = __float_as_uint(sB[j * SKP + kb]);
            ub[ni][1] = __float_as_uint(sB[j * SKP + kb + 4]);
        }
#pragma unroll
        for (int mi = 0; mi < 2; mi++)
#pragma unroll
            for (int ni = 0; ni < 2; ni++)
                mma8(acc1[mi][ni], ua[mi], ub[ni]);
    }
    __syncthreads();

    // mask + scale into G (tf32-rounded at write; overwrites sC)
#pragma unroll
    for (int mi = 0; mi < 2; mi++) {
        int ilo = wm0 + mi * 16 + gr;
        int ihi = ilo + 8;
#pragma unroll
        for (int ni = 0; ni < 2; ni++) {
            int j0c = wn0 + ni * 8 + 2 * lk;
            int j1c = j0c + 1;
            float g00 = (j0c <= ilo) ? acc1[mi][ni][0] * sdt[j0c] * expf(sla[ilo] - sla[j0c]) : 0.f;
            float g01 = (j1c <= ilo) ? acc1[mi][ni][1] * sdt[j1c] * expf(sla[ilo] - sla[j1c]) : 0.f;
            float g10 = (j0c <= ihi) ? acc1[mi][ni][2] * sdt[j0c] * expf(sla[ihi] - sla[j0c]) : 0.f;
            float g11 = (j1c <= ihi) ? acc1[mi][ni][3] * sdt[j1c] * expf(sla[ihi] - sla[j1c]) : 0.f;
            sC[ilo * SKP + j0c] = tfr(g00);
            sC[ilo * SKP + j1c] = tfr(g01);
            sC[ihi * SKP + j0c] = tfr(g10);
            sC[ihi * SKP + j1c] = tfr(g11);
        }
    }
    __syncthreads();

    // --- GEMM2: Y[i][p] = sum_j G[i,j] * X[j,p]  (both pre-rounded) ---
    {
        float acc2[2][2][4];
#pragma unroll
        for (int mi = 0; mi < 2; mi++)
#pragma unroll
            for (int ni = 0; ni < 2; ni++)
#pragma unroll
                for (int e = 0; e < 4; e++) acc2[mi][ni][e] = 0.f;

#pragma unroll
        for (int k8 = 0; k8 < 8; k8++) {
            int kb = k8 * 8 + lk;
            uint32_t ua[2][4], ub[2][2];
#pragma unroll
            for (int mi = 0; mi < 2; mi++) {
                int r = wm0 + mi * 16 + gr;
                ua[mi][0] = __float_as_uint(sC[r * SKP + kb]);
                ua[mi][1] = __float_as_uint(sC[(r + 8) * SKP + kb]);
                ua[mi][2] = __float_as_uint(sC[r * SKP + kb + 4]);
                ua[mi][3] = __float_as_uint(sC[(r + 8) * SKP + kb + 4]);
            }
#pragma unroll
            for (int ni = 0; ni < 2; ni++) {
                int p = wn0 + ni * 8 + gr;
                ub[ni][0] = __float_as_uint(sX[kb * SKP + p]);
                ub[ni][1] = __float_as_uint(sX[(kb + 4) * SKP + p]);
            }
#pragma unroll
            for (int mi = 0; mi < 2; mi++)
#pragma unroll
                for (int ni = 0; ni < 2; ni++)
                    mma8(acc2[mi][ni], ua[mi], ub[ni]);
        }
#pragma unroll
        for (int mi = 0; mi < 2; mi++) {
            int ilo = wm0 + mi * 16 + gr;
#pragma unroll
            for (int ni = 0; ni < 2; ni++) {
                int pc = wn0 + ni * 8 + 2 * lk;
                *(float2*)(yintra + (size_t)(row0 + ilo) * D_SSM + h * HEADDIM + pc) =
                    make_float2(acc2[mi][ni][0], acc2[mi][ni][1]);
                *(float2*)(yintra + (size_t)(row0 + ilo + 8) * D_SSM + h * HEADDIM + pc) =
                    make_float2(acc2[mi][ni][2], acc2[mi][ni][3]);
            }
        }
    }

    // --- GEMM3: T[p][n] = sum_j (w_j * X[j,p]) * B[j,n] ---
    {
        float acc3[2][2][4];
#pragma unroll
        for (int mi = 0; mi < 2; mi++)
#pragma unroll
            for (int ni = 0; ni < 2; ni++)
#pragma unroll
                for (int e = 0; e < 4; e++) acc3[mi][ni][e] = 0.f;

#pragma unroll
        for (int k8 = 0; k8 < 8; k8++) {
            int kb = k8 * 8 + lk;
            float w0 = sw[kb], w1 = sw[kb + 4];
            uint32_t ua[2][4], ub[2][2];
#pragma unroll
            for (int mi = 0; mi < 2; mi++) {
                int r = wm0 + mi * 16 + gr;   // p index
                ua[mi][0] = f2tf(sX[kb * SKP + r] * w0);
                ua[mi][1] = f2tf(sX[kb * SKP + r + 8] * w0);
                ua[mi][2] = f2tf(sX[(kb + 4) * SKP + r] * w1);
                ua[mi][3] = f2tf(sX[(kb + 4) * SKP + r + 8] * w1);
            }
#pragma unroll
            for (int ni = 0; ni < 2; ni++) {
                int n = wn0 + ni * 8 + gr;
                ub[ni][0] = __float_as_uint(sB[kb * SKP + n]);
                ub[ni][1] = __float_as_uint(sB[(kb + 4) * SKP + n]);
            }
#pragma unroll
            for (int mi = 0; mi < 2; mi++)
#pragma unroll
                for (int ni = 0; ni < 2; ni++)
                    mma8(acc3[mi][ni], ua[mi], ub[ni]);
        }
#pragma unroll
        for (int mi = 0; mi < 2; mi++) {
            int plo = wm0 + mi * 16 + gr;
#pragma unroll
            for (int ni = 0; ni < 2; ni++) {
                int nc = wn0 + ni * 8 + 2 * lk;
                *(float2*)(Tg + (size_t)bhc * 4096 + plo * 64 + nc) =
                    make_float2(acc3[mi][ni][0], acc3[mi][ni][1]);
                *(float2*)(Tg + (size_t)bhc * 4096 + (plo + 8) * 64 + nc) =
                    make_float2(acc3[mi][ni][2], acc3[mi][ni][3]);
            }
        }
    }
}

// ---------------------------------------------------------------------------
// Parallel chunk-state combine: 768 blocks; Sg written tf32-rounded.
// ---------------------------------------------------------------------------
__global__ __launch_bounds__(256) void combine_kernel(
    const float* __restrict__ Tg, const float* __restrict__ laendg,
    float* __restrict__ Sg)
{
    const int bh  = blockIdx.x >> 4;
    const int e   = (blockIdx.x & 15) * 256 + threadIdx.x;
    float s = 0.f;
#pragma unroll
    for (int c = 0; c < NCHUNK; c++) {
        int bhc = bh * NCHUNK + c;
        Sg[(size_t)bhc * 4096 + e] = tfr(s);
        float ae = expf(__ldg(laendg + bhc));
        s = fmaf(ae, s, Tg[(size_t)bhc * 4096 + e]);
    }
}

// ---------------------------------------------------------------------------
// Inter-chunk contribution + skip + gating — tf32 mma; SKP-padded smem with
// float4 staging; writes y rounded to tf32 for out_proj.
// ---------------------------------------------------------------------------
__global__ __launch_bounds__(256) void inter_kernel(
    const float* __restrict__ xbc, const float* __restrict__ Sg,
    const float* __restrict__ aig, const float* __restrict__ zx,
    const float* __restrict__ Dp, float* __restrict__ y)
{
    __shared__ float sC[TILE_F];
    __shared__ float sS[TILE_F];
    __shared__ float sai[64];

    const int bhc = blockIdx.x;
    const int c = bhc & (NCHUNK - 1);
    const int h = (bhc >> 3) % NHEADS;
    const int b = bhc / (NCHUNK * NHEADS);
    const int tid  = threadIdx.x;
    const int lane = tid & 31;
    const int warp = tid >> 5;
    const int gr   = lane >> 2;
    const int lk   = lane & 3;
    const int wm0  = (warp & 1) * 32;
    const int wn0  = (warp >> 1) * 16;
    const int row0 = b * LL + c * QC;

#pragma unroll
    for (int idx = tid; idx < 64 * 16; idx += 256) {
        int i = idx >> 4, f = idx & 15;
        const float* rp = xbc + (size_t)(row0 + i) * CONV_DIM;
        float4 cv = *(const float4*)(rp + D_SSM + D_STATE + f * 4);
        *(float4*)(sC + i * SKP + f * 4) = cv;
        float4 sv = *(const float4*)(Sg + (size_t)bhc * 4096 + i * 64 + f * 4);
        *(float4*)(sS + i * SKP + f * 4) = sv;
    }
    if (tid < 64) sai[tid] = aig[bhc * QC + tid];
    __syncthreads();

    float acc[2][2][4];
#pragma unroll
    for (int mi = 0; mi < 2; mi++)
#pragma unroll
        for (int ni = 0; ni < 2; ni++)
#pragma unroll
            for (int e = 0; e < 4; e++) acc[mi][ni][e] = 0.f;

#pragma unroll
    for (int k8 = 0; k8 < 8; k8++) {
        int kb = k8 * 8 + lk;
        uint32_t ua[2][4], ub[2][2];
#pragma unroll
        for (int mi = 0; mi < 2; mi++) {
            int r = wm0 + mi * 16 + gr;
            ua[mi][0] = __float_as_uint(sC[r * SKP + kb]);
            ua[mi][1] = __float_as_uint(sC[(r + 8) * SKP + kb]);
            ua[mi][2] = __float_as_uint(sC[r * SKP + kb + 4]);
            ua[mi][3] = __float_as_uint(sC[(r + 8) * SKP + kb + 4]);
        }
#pragma unroll
        for (int ni = 0; ni < 2; ni++) {
            int p = wn0 + ni * 8 + gr;
            ub[ni][0] = __float_as_uint(sS[p * SKP + kb]);
            ub[ni][1] = __float_as_uint(sS[p * SKP + kb + 4]);
        }
#pragma unroll
        for (int mi = 0; mi < 2; mi++)
#pragma unroll
            for (int ni = 0; ni < 2; ni++)
                mma8(acc[mi][ni], ua[mi], ub[ni]);
    }

    const float Dv = Dp[h];
#pragma unroll
    for (int mi = 0; mi < 2; mi++) {
        int rows[2] = { wm0 + mi * 16 + gr, wm0 + mi * 16 + gr + 8 };
#pragma unroll
        for (int rr = 0; rr < 2; rr++) {
            int i = rows[rr];
            size_t r = row0 + i;
            float aiv = sai[i];
#pragma unroll
            for (int ni = 0; ni < 2; ni++) {
                int pc = wn0 + ni * 8 + 2 * lk;
                float a0 = acc[mi][ni][rr * 2 + 0];
                float a1 = acc[mi][ni][rr * 2 + 1];
                float2 xv = *(const float2*)(xbc + r * CONV_DIM + h * HEADDIM + pc);
                float2 zv = *(const float2*)(zx + r * D_IN_PROJ + h * HEADDIM + pc);
                float2 yv = *(float2*)(y + r * D_SSM + h * HEADDIM + pc);
                float y0 = yv.x + aiv * a0 + Dv * xv.x;
                float y1 = yv.y + aiv * a1 + Dv * xv.y;
                y0 *= zv.x * (1.f / (1.f + expf(-zv.x)));
                y1 *= zv.y * (1.f / (1.f + expf(-zv.y)));
                *(float2*)(y + r * D_SSM + h * HEADDIM + pc) =
                    make_float2(tfr(y0), tfr(y1));
            }
        }
    }
}

// ---------------------------------------------------------------------------
// Launch — single-stream R16 pipeline
// ---------------------------------------------------------------------------
extern "C" void kernel_launch(void* const* d_in, const int* in_sizes, int n_in,
                              void* d_out, int out_size)
{
    const float* u       = (const float*)d_in[0];
    const float* W_in    = (const float*)d_in[1];
    const float* conv_w  = (const float*)d_in[2];
    const float* conv_b  = (const float*)d_in[3];
    const float* dt_bias = (const float*)d_in[4];
    const float* A_log   = (const float*)d_in[5];
    const float* D_param = (const float*)d_in[6];
    const float* W_out   = (const float*)d_in[7];
    float* out = (float*)d_out;

    float *zx, *xbc, *dt, *ldA, *y, *Tg, *Sg, *aig, *laendg, *uc, *Wic, *Woc;
    cudaGetSymbolAddress((void**)&zx,     g_zxbcdt);
    cudaGetSymbolAddress((void**)&xbc,    g_xbc);
    cudaGetSymbolAddress((void**)&dt,     g_dt);
    cudaGetSymbolAddress((void**)&ldA,    g_ldA);
    cudaGetSymbolAddress((void**)&y,      g_y);
    cudaGetSymbolAddress((void**)&Tg,     g_T);
    cudaGetSymbolAddress((void**)&Sg,     g_S);
    cudaGetSymbolAddress((void**)&aig,    g_ai);
    cudaGetSymbolAddress((void**)&laendg, g_laend);
    cudaGetSymbolAddress((void**)&uc,     g_uc);
    cudaGetSymbolAddress((void**)&Wic,    g_Wic);
    cudaGetSymbolAddress((void**)&Woc,    g_Woc);

    static bool attr_done = false;
    if (!attr_done) {
        cudaFuncSetAttribute(chunk_kernel,
                             cudaFuncAttributeMaxDynamicSharedMemorySize,
                             (3 * TILE_F + 192) * 4);
        cudaFuncSetAttribute(mma_gemm<64, 128>,
                             cudaFuncAttributeMaxDynamicSharedMemorySize, 55296);
        cudaFuncSetAttribute(mma_gemm<64, 64>,
                             cudaFuncAttributeMaxDynamicSharedMemorySize, 36864);
        attr_done = true;
    }

    // 0) tf32 pre-round of u, W_in, W_out
    {
        int n4 = (UN_F + WIN_F + WOUT_F) / 4;
        tf32_prep_kernel<<<(n4 + 255) / 256, 256>>>(
            (const float4*)u, (const float4*)W_in, (const float4*)W_out,
            (float4*)uc, (float4*)Wic, (float4*)Woc);
    }

    // 1) in_proj: 64x128 tiles, 416 blocks; pre-rounded 1x except
    //    B/C block-col [3072,3200) tf32x3 (raw)
    {
        dim3 grid(26, BL / 64);
        mma_gemm<64, 128><<<grid, 256, 55296>>>(
            uc, u, Wic, W_in, zx, D_IN_PROJ, D_IN_PROJ, D_IN_PROJ, D_MODEL,
            3072, 3200);
    }
    // 2) conv + silu + dt/ldA (2D grid, div-free conv path)
    {
        dim3 grid(14, 256);
        conv_dt_kernel<<<grid, 128>>>(
            zx, conv_w, conv_b, dt_bias, A_log, xbc, dt, ldA);
    }
    // 3) chunked scan (SKP-padded smem, float4 staging)
    chunk_kernel<<<NBHC, 256, (3 * TILE_F + 192) * 4>>>(
        xbc, dt, ldA, y, Tg, aig, laendg);
    combine_kernel<<<BB * NHEADS * 16, 256>>>(Tg, laendg, Sg);
    inter_kernel<<<NBHC, 256>>>(xbc, Sg, aig, zx, D_param, y);

    // 4) out_proj: 64x64 tiles, 192 blocks
    {
        dim3 grid(D_MODEL / 64, BL / 64);
        mma_gemm<64, 64><<<grid, 256, 36864>>>(
            y, y, Woc, W_out, out, D_MODEL, D_MODEL, D_MODEL, D_SSM,
            1 << 30, 1 << 30);
    }
}